// round 6
// baseline (speedup 1.0000x reference)
#include <cuda_runtime.h>
#include <math.h>
#include <stdint.h>

#define BATCH 4
#define LSEQ  512
#define DMODEL 512
#define DFF   512
#define DINNER 256
#define MR    (BATCH*LSEQ)   /* 2048 rows */
#define MR2   (2*MR)         /* 4096 rows: merged pair */

__device__ __align__(16) float g_scratch[26u*1024u*1024u];

__device__ __forceinline__ float siluf(float x){ return x / (1.0f + expf(-x)); }
__device__ __forceinline__ float softplusf(float x){ return (x > 20.0f) ? x : log1pf(expf(x)); }

__device__ __forceinline__ uint32_t f2tf32(float x){
    uint32_t r; asm("cvt.rna.tf32.f32 %0, %1;" : "=r"(r) : "f"(x)); return r;
}
__device__ __forceinline__ void mma_tf32(float* c, const uint32_t* a, const uint32_t* b){
    asm volatile("mma.sync.aligned.m16n8k8.row.col.f32.tf32.tf32.f32 "
        "{%0,%1,%2,%3}, {%4,%5,%6,%7}, {%8,%9}, {%0,%1,%2,%3};"
        : "+f"(c[0]),"+f"(c[1]),"+f"(c[2]),"+f"(c[3])
        : "r"(a[0]),"r"(a[1]),"r"(a[2]),"r"(a[3]), "r"(b[0]),"r"(b[1]));
}

// ---------------------------------------------------------------------------
// TF32 tensor-core GEMM, compile-time fused variants.
//   C = act((A [+A2 if FA2]) @ W + bias) [+ P1.*P2 if FP] [+ C if ACC]
//   FLIP: A row index flipped within 512-row blocks.
// 128x64 tile, 256 threads (8 warps 4x2), warp tile 32x32 (2x4 m16n8k8).
// K-chunk 16, double-buffered smem, 2-chunk register prefetch.
// M%128==0, K%16==0, N arbitrary. Batched/split via blockIdx.z.
// ---------------------------------------------------------------------------
template<int ACT, int ACC, int FA2, int FP, int FLIP>
__global__ __launch_bounds__(256)
void gemm_tc(const float* __restrict__ A, const float* __restrict__ A2,
             const float* __restrict__ W,
             const float* __restrict__ bias, long long biasb,
             const float* __restrict__ P1, int ldp1, long long p1b,
             const float* __restrict__ P2, int ldp2, long long p2b,
             float* __restrict__ C,
             int M, int N, int K, int lda, int ldw, int ldc,
             long long Ab, long long Wb, long long Cb)
{
    __shared__ uint32_t As[2][128][20];
    __shared__ uint32_t Bs[2][16][72];
    const int bz = blockIdx.z;
    A += (long long)bz * Ab;  W += (long long)bz * Wb;  C += (long long)bz * Cb;
    if (FA2) A2 += (long long)bz * Ab;
    if (FP) { P1 += (long long)bz * p1b; P2 += (long long)bz * p2b; }
    const float* biasp = bias ? (bias + (long long)bz * biasb) : nullptr;
    const int t = threadIdx.x;
    const int lane = t & 31, wid = t >> 5;
    const int wm = wid >> 1, wn = wid & 1;
    const int gp = lane >> 2, tg = lane & 3;
    const int row0 = blockIdx.y * 128, col0 = blockIdx.x * 64;
    const int a_r = t >> 1, a_k = (t & 1) * 8;
    const int b_k = t >> 4, b_n = (t & 15) * 4;

    int rowA = row0 + a_r;
    if (FLIP) rowA = (rowA & ~(LSEQ-1)) | ((LSEQ-1) - (rowA & (LSEQ-1)));
    const float* Arow  = A + (long long)rowA * lda;
    const float* A2row = FA2 ? (A2 + (long long)rowA * lda) : nullptr;

    float c[2][4][4] = {};
    float4 pA0[2], pA1[2], pB[2];

    const int nc = K >> 4;
    #pragma unroll
    for (int p = 0; p < 2; p++) {
        if (p < nc) {
            const float* ap = Arow + p*16 + a_k;
            float4 a0 = *(const float4*)ap, a1 = *(const float4*)(ap + 4);
            if (FA2) {
                const float* ap2 = A2row + p*16 + a_k;
                float4 b0 = *(const float4*)ap2, b1 = *(const float4*)(ap2 + 4);
                a0.x+=b0.x; a0.y+=b0.y; a0.z+=b0.z; a0.w+=b0.w;
                a1.x+=b1.x; a1.y+=b1.y; a1.z+=b1.z; a1.w+=b1.w;
            }
            pA0[p] = a0; pA1[p] = a1;
            int gn = col0 + b_n;
            const float* wp = W + (long long)(p*16 + b_k) * ldw + gn;
            float4 bv;
            if (gn + 3 < N) bv = *(const float4*)wp;
            else {
                bv.x=(gn<N)?wp[0]:0.f; bv.y=(gn+1<N)?wp[1]:0.f;
                bv.z=(gn+2<N)?wp[2]:0.f; bv.w=(gn+3<N)?wp[3]:0.f;
            }
            pB[p] = bv;
        }
    }

    for (int i = 0; i < nc; i++) {
        const int s = i & 1;
        {
            uint32_t* as = &As[s][a_r][a_k];
            float4 a0 = pA0[s], a1 = pA1[s];
            as[0]=f2tf32(a0.x); as[1]=f2tf32(a0.y); as[2]=f2tf32(a0.z); as[3]=f2tf32(a0.w);
            as[4]=f2tf32(a1.x); as[5]=f2tf32(a1.y); as[6]=f2tf32(a1.z); as[7]=f2tf32(a1.w);
            uint32_t* bs = &Bs[s][b_k][b_n];
            float4 bv = pB[s];
            bs[0]=f2tf32(bv.x); bs[1]=f2tf32(bv.y); bs[2]=f2tf32(bv.z); bs[3]=f2tf32(bv.w);
        }
        __syncthreads();
        if (i + 2 < nc) {
            const int kb = (i + 2) * 16;
            const float* ap = Arow + kb + a_k;
            float4 a0 = *(const float4*)ap, a1 = *(const float4*)(ap + 4);
            if (FA2) {
                const float* ap2 = A2row + kb + a_k;
                float4 b0 = *(const float4*)ap2, b1 = *(const float4*)(ap2 + 4);
                a0.x+=b0.x; a0.y+=b0.y; a0.z+=b0.z; a0.w+=b0.w;
                a1.x+=b1.x; a1.y+=b1.y; a1.z+=b1.z; a1.w+=b1.w;
            }
            pA0[s] = a0; pA1[s] = a1;
            int gn = col0 + b_n;
            const float* wp = W + (long long)(kb + b_k) * ldw + gn;
            float4 bv;
            if (gn + 3 < N) bv = *(const float4*)wp;
            else {
                bv.x=(gn<N)?wp[0]:0.f; bv.y=(gn+1<N)?wp[1]:0.f;
                bv.z=(gn+2<N)?wp[2]:0.f; bv.w=(gn+3<N)?wp[3]:0.f;
            }
            pB[s] = bv;
        }
        #pragma unroll
        for (int ks = 0; ks < 2; ks++) {
            const int k0 = ks * 8;
            uint32_t a[2][4], b[4][2];
            #pragma unroll
            for (int mb = 0; mb < 2; mb++) {
                int r0 = wm*32 + mb*16 + gp;
                a[mb][0] = As[s][r0  ][k0 + tg];
                a[mb][1] = As[s][r0+8][k0 + tg];
                a[mb][2] = As[s][r0  ][k0 + 4 + tg];
                a[mb][3] = As[s][r0+8][k0 + 4 + tg];
            }
            #pragma unroll
            for (int nb = 0; nb < 4; nb++) {
                int cc = wn*32 + nb*8 + gp;
                b[nb][0] = Bs[s][k0 + tg    ][cc];
                b[nb][1] = Bs[s][k0 + 4 + tg][cc];
            }
            #pragma unroll
            for (int mb = 0; mb < 2; mb++)
                #pragma unroll
                for (int nb = 0; nb < 4; nb++)
                    mma_tf32(c[mb][nb], a[mb], b[nb]);
        }
    }

    #pragma unroll
    for (int mb = 0; mb < 2; mb++) {
        #pragma unroll
        for (int half = 0; half < 2; half++) {
            long long gr = row0 + wm*32 + mb*16 + gp + half*8;
            #pragma unroll
            for (int nb = 0; nb < 4; nb++) {
                #pragma unroll
                for (int j = 0; j < 2; j++) {
                    int gn = col0 + wn*32 + nb*8 + tg*2 + j;
                    if (gn < N) {
                        float v = c[mb][nb][half*2 + j];
                        if (biasp) v += biasp[gn];
                        if (ACT==1) v = siluf(v);
                        if (ACT==2) v = softplusf(v);
                        if (FP) v += P1[gr*ldp1 + gn] * P2[gr*ldp2 + gn];
                        if (ACC) v += C[gr*ldc + gn];
                        C[gr*ldc + gn] = v;
                    }
                }
            }
        }
    }
}

// ---------------------------------------------------------------------------
// hs0(2048x1024) -> stacked silu / flipped-silu pairs
// ---------------------------------------------------------------------------
__global__ void silu_flip_k(const float* __restrict__ hs0, float* __restrict__ sx,
                            float* __restrict__ sz, float* __restrict__ fx,
                            float* __restrict__ fz)
{
    int i = blockIdx.x*256 + threadIdx.x;
    if (i >= MR*DFF) return;
    int d = i & (DFF-1);
    int m = i >> 9;
    int b = m >> 9, tt = m & (LSEQ-1);
    float s1 = siluf(hs0[m*1024 + d]);
    float s2 = siluf(hs0[m*1024 + 512 + d]);
    sx[i] = s1; sz[i] = s2;
    int mf = (b << 9) + (LSEQ-1 - tt);
    fx[mf*DFF + d] = siluf(s1);
    fz[mf*DFF + d] = siluf(s2);
}

// ---------------------------------------------------------------------------
// Selective scan over nseq sequences of length LSEQ. Thread per (seq,d,n).
// ---------------------------------------------------------------------------
__global__ void scan_k(const float* __restrict__ delta, const float* __restrict__ u,
                       const float* __restrict__ Bm, int ldb,
                       const float* __restrict__ Alog,
                       float* __restrict__ hsum, int D, int nseq)
{
    int tid = blockIdx.x*256 + threadIdx.x;
    int n = tid & 15;
    int seg = tid >> 4;
    int d = seg % D;
    int s = seg / D;
    if (s >= nseq) return;
    float An = -expf(Alog[n]);
    float h = 0.f;
    int base = s * LSEQ;
    #pragma unroll 4
    for (int ts = 0; ts < LSEQ; ts++) {
        int r = base + ts;
        float dl = delta[r*D + d];
        float ul = u[r*D + d];
        float Bv = Bm[(long long)r*ldb + n];
        float a = expf(dl * An);
        h = fmaf(a, h, dl * ul * Bv);
        float v = h;
        v += __shfl_xor_sync(0xffffffffu, v, 1);
        v += __shfl_xor_sync(0xffffffffu, v, 2);
        v += __shfl_xor_sync(0xffffffffu, v, 4);
        v += __shfl_xor_sync(0xffffffffu, v, 8);
        if (n == 0) hsum[r*D + d] = v;
    }
}

// ---------------------------------------------------------------------------
// Fused skinny projections: q = softplus(u@qw+qb), k = softplus(Cm@kw+kb)
// ---------------------------------------------------------------------------
__global__ void qk_k(const float* __restrict__ u, int D,
                     const float* __restrict__ qw, const float* __restrict__ qb,
                     const float* __restrict__ dbcd, int Np,
                     const float* __restrict__ kw, const float* __restrict__ kb,
                     float* __restrict__ qbuf, float* __restrict__ kbuf)
{
    int t = threadIdx.x;
    int c = t & 15, r16 = t >> 4;
    long long row = (long long)blockIdx.x * 16 + r16;
    const float* ar = u + row * D;
    float acc = 0.f;
    #pragma unroll 4
    for (int k = 0; k < D; k += 4) {
        float4 a4 = *(const float4*)(ar + k);
        acc = fmaf(a4.x, qw[(k+0)*16 + c], acc);
        acc = fmaf(a4.y, qw[(k+1)*16 + c], acc);
        acc = fmaf(a4.z, qw[(k+2)*16 + c], acc);
        acc = fmaf(a4.w, qw[(k+3)*16 + c], acc);
    }
    qbuf[row*16 + c] = softplusf(acc + qb[c]);
    const float* cr = dbcd + row * Np + 48;
    float acck = 0.f;
    #pragma unroll
    for (int k = 0; k < 16; k++) acck = fmaf(cr[k], kw[k*16 + c], acck);
    kbuf[row*16 + c] = softplusf(acck + kb[c]);
}

// ---------------------------------------------------------------------------
// attn[s,i,j] = softmax_j( dot(q[s,i,:], k[s,j,:]) / 16 ).  Block per (i,s).
// ---------------------------------------------------------------------------
__global__ void attn_k(const float* __restrict__ q, const float* __restrict__ k,
                       float* __restrict__ attn)
{
    const int i = blockIdx.x, s = blockIdx.y;
    __shared__ float qs[16];
    __shared__ float red[16];
    const int t = threadIdx.x;  // 256
    if (t < 16) qs[t] = q[(s*LSEQ + i)*16 + t];
    __syncthreads();
    float v[2];
    #pragma unroll
    for (int jj = 0; jj < 2; jj++) {
        int j = t + jj*256;
        const float4* kr = (const float4*)(k + (long long)(s*LSEQ + j)*16);
        float4 k0 = kr[0], k1 = kr[1], k2 = kr[2], k3 = kr[3];
        float sc = qs[0]*k0.x + qs[1]*k0.y + qs[2]*k0.z + qs[3]*k0.w
                 + qs[4]*k1.x + qs[5]*k1.y + qs[6]*k1.z + qs[7]*k1.w
                 + qs[8]*k2.x + qs[9]*k2.y + qs[10]*k2.z + qs[11]*k2.w
                 + qs[12]*k3.x + qs[13]*k3.y + qs[14]*k3.z + qs[15]*k3.w;
        v[jj] = sc * (1.0f/16.0f);
    }
    float m = fmaxf(v[0], v[1]);
    for (int o=16;o;o>>=1) m = fmaxf(m, __shfl_xor_sync(0xffffffffu, m, o));
    if ((t&31)==0) red[t>>5] = m;
    __syncthreads();
    if (t == 0) { float mm = red[0]; for (int w=1;w<8;w++) mm = fmaxf(mm, red[w]); red[0] = mm; }
    __syncthreads();
    float bm = red[0];
    v[0] = expf(v[0]-bm); v[1] = expf(v[1]-bm);
    float sm = v[0] + v[1];
    for (int o=16;o;o>>=1) sm += __shfl_xor_sync(0xffffffffu, sm, o);
    if ((t&31)==0) red[8 + (t>>5)] = sm;
    __syncthreads();
    if (t == 0) { float ss = 0.f; for (int w=0;w<8;w++) ss += red[8+w]; red[8] = ss; }
    __syncthreads();
    float inv = 1.0f / red[8];
    float* arow = attn + ((long long)s*LSEQ + i)*LSEQ;
    arow[t]     = v[0]*inv;
    arow[t+256] = v[1]*inv;
}

// ---------------------------------------------------------------------------
// Host side
// ---------------------------------------------------------------------------
struct GArgs {
    const float *A, *A2, *W, *bias; long long biasb;
    const float *P1; int ldp1; long long p1b;
    const float *P2; int ldp2; long long p2b;
    float* C; int M, N, K, lda, ldw, ldc;
    int bat; long long Ab, Wb, Cb;
};

template<int ACT, int ACC, int FA2, int FP, int FLIP>
static inline void rungemm(const GArgs& g)
{
    dim3 gr((g.N + 63) / 64, g.M / 128, g.bat), bl(256);
    gemm_tc<ACT,ACC,FA2,FP,FLIP><<<gr, bl>>>(g.A, g.A2, g.W, g.bias, g.biasb,
        g.P1, g.ldp1, g.p1b, g.P2, g.ldp2, g.p2b,
        g.C, g.M, g.N, g.K, g.lda, g.ldw, g.ldc, g.Ab, g.Wb, g.Cb);
}

static inline GArgs GA(const float* A, const float* W, const float* bias, float* C,
                       int M, int N, int K, int lda, int ldw, int ldc)
{
    GArgs g{}; g.A=A; g.A2=nullptr; g.W=W; g.bias=bias; g.biasb=0;
    g.P1=nullptr; g.ldp1=0; g.p1b=0; g.P2=nullptr; g.ldp2=0; g.p2b=0;
    g.C=C; g.M=M; g.N=N; g.K=K; g.lda=lda; g.ldw=ldw; g.ldc=ldc;
    g.bat=1; g.Ab=0; g.Wb=0; g.Cb=0;
    return g;
}

// Merged-pair SSM on u [4096 x D]
static void ssm_run2(const float* u, int D, const float* projw, int Np,
                     const float* dtw, const float* dtb, const float* Alog,
                     const float* qw, const float* qb, const float* kw, const float* kb,
                     bool useD, float* yout,
                     float* dbcd, float* delta, float* hsum, float* qbuf, float* kbuf,
                     float* attn)
{
    rungemm<0,0,0,0,0>(GA(u, projw, nullptr, dbcd, MR2, Np, D, D, Np, Np));
    rungemm<2,0,0,0,0>(GA(dbcd, dtw, dtb, delta, MR2, D, 32, Np, D, D));   // softplus
    scan_k<<<(8*D*16)/256, 256>>>(delta, u, dbcd + 32, Np, Alog, hsum, D, 8);
    qk_k<<<MR2/16, 256>>>(u, D, qw, qb, dbcd, Np, kw, kb, qbuf, kbuf);
    attn_k<<<dim3(LSEQ, 8), 256>>>(qbuf, kbuf, attn);
    GArgs g = GA(attn, hsum, nullptr, yout, LSEQ, D, LSEQ, LSEQ, D, D);
    g.bat = 8; g.Ab = (long long)LSEQ*LSEQ; g.Wb = (long long)LSEQ*D; g.Cb = (long long)LSEQ*D;
    if (useD) {
        g.P1 = dbcd + 64; g.ldp1 = Np; g.p1b = (long long)LSEQ*Np;
        g.P2 = u;        g.ldp2 = D;  g.p2b = (long long)LSEQ*D;
        rungemm<0,0,0,1,0>(g);
    } else {
        rungemm<0,0,0,0,0>(g);
    }
}

extern "C" void kernel_launch(void* const* d_in, const int* in_sizes, int n_in,
                              void* d_out, int out_size)
{
    (void)in_sizes; (void)n_in; (void)out_size;
    float* S = nullptr;
    cudaGetSymbolAddress((void**)&S, g_scratch);

    float* hs0   = S;                 // 2048*1024
    float* usx   = hs0   + 2097152;   // [4096 x 512]
    float* ufb   = usx   + 2097152;   // [4096 x 512]
    float* ub    = ufb   + 2097152;   // [4096 x 256]
    float* dbcd  = ub    + 1048576;   // 4096*576
    float* delta = dbcd  + 2359296;   // 4096*512
    float* hsum  = delta + 2097152;   // 4096*512
    float* qbuf  = hsum  + 2097152;   // 4096*16
    float* kbuf  = qbuf  + 65536;
    float* attn  = kbuf  + 65536;     // 8*512*512
    float* yfwd  = attn  + 2097152;   // [4096 x 512]
    float* ybwd  = yfwd  + 2097152;   // [4096 x 256]
    float* cat2  = ybwd  + 1048576;   // 2048*1024
    float* oe    = cat2  + 2097152;   // 2048*256
    float* xbuf  = oe    + 524288;    // 2048*512

    const float* x             = (const float*)d_in[0];
    const float* in_w          = (const float*)d_in[1];
    const float* in_b          = (const float*)d_in[2];
    const float* x_proj_w      = (const float*)d_in[3];
    const float* dt_w          = (const float*)d_in[4];
    const float* dt_b          = (const float*)d_in[5];
    const float* A_log         = (const float*)d_in[6];
    const float* exit_x_w      = (const float*)d_in[7];
    const float* exit_x_b      = (const float*)d_in[8];
    const float* exit_z_w      = (const float*)d_in[9];
    const float* exit_z_b      = (const float*)d_in[10];
    const float* x_proj_exit_w = (const float*)d_in[11];
    const float* dt_exit_w     = (const float*)d_in[12];
    const float* dt_exit_b     = (const float*)d_in[13];
    const float* A_log_exit    = (const float*)d_in[14];
    const float* out_inner_w   = (const float*)d_in[15];
    const float* out_inner_b   = (const float*)d_in[16];
    const float* out_exit_w    = (const float*)d_in[17];
    const float* out_exit_b    = (const float*)d_in[18];
    const float* up_w          = (const float*)d_in[19];
    const float* up_b          = (const float*)d_in[20];
    const float* out_w         = (const float*)d_in[21];
    const float* out_b         = (const float*)d_in[22];
    const float* q_in_w        = (const float*)d_in[23];
    const float* q_in_b        = (const float*)d_in[24];
    const float* k_in_w        = (const float*)d_in[25];
    const float* k_in_b        = (const float*)d_in[26];
    const float* q_ex_w        = (const float*)d_in[27];
    const float* q_ex_b        = (const float*)d_in[28];
    const float* k_ex_w        = (const float*)d_in[29];
    const float* k_ex_b        = (const float*)d_in[30];

    const float* cur = x;
    for (int l = 0; l < 2; l++) {
        const float* in_w_l = in_w + (long long)l*512*1024;
        const float* in_b_l = in_b + l*1024;
        const float* xp_l   = x_proj_w + (long long)l*512*576;
        const float* dtw_l  = dt_w + l*32*512;
        const float* dtb_l  = dt_b + l*512;
        const float* Al_l   = A_log + l*16;
        const float* exw_l  = exit_x_w + (long long)l*512*256;
        const float* exb_l  = exit_x_b + l*256;
        const float* ezw_l  = exit_z_w + (long long)l*512*256;
        const float* ezb_l  = exit_z_b + l*256;
        const float* xpe_l  = x_proj_exit_w + (long long)l*256*320;
        const float* dtew_l = dt_exit_w + l*32*256;
        const float* dteb_l = dt_exit_b + l*256;
        const float* Ale_l  = A_log_exit + l*16;
        const float* oiw_l  = out_inner_w + (long long)l*1024*512;
        const float* oib_l  = out_inner_b + l*512;
        const float* oew_l  = out_exit_w + (long long)l*512*256;
        const float* oeb_l  = out_exit_b + l*256;
        const float* upw_l  = up_w + (long long)l*256*512;
        const float* upb_l  = up_b + l*512;
        const float* ow_l   = out_w + (long long)l*1024*512;
        const float* ob_l   = out_b + l*512;
        const float* qiw_l  = q_in_w + l*512*16;
        const float* qib_l  = q_in_b + l*16;
        const float* kiw_l  = k_in_w + l*16*16;
        const float* kib_l  = k_in_b + l*16;
        const float* qew_l  = q_ex_w + l*256*16;
        const float* qeb_l  = q_ex_b + l*16;
        const float* kew_l  = k_ex_w + l*16*16;
        const float* keb_l  = k_ex_b + l*16;

        // 1. hs0 = cur @ in_w + in_b   (2048 x 1024)
        rungemm<0,0,0,0,0>(GA(cur, in_w_l, in_b_l, hs0, MR, 1024, 512, 512, 1024, 1024));
        // 2. activations + flipped inputs
        silu_flip_k<<<(MR*DFF)/256, 256>>>(hs0, usx, usx + MR*DFF, ufb, ufb + MR*DFF);
        // 3. backward-path inputs as ONE batched launch
        {
            GArgs g = GA(ufb, exw_l, exb_l, ub, MR, 256, 512, 512, 256, 256);
            g.bat = 2;
            g.Ab = (long long)MR*512;
            g.Wb = (long long)(ezw_l - exw_l);
            g.biasb = (long long)(ezb_l - exb_l);
            g.Cb = (long long)MR*256;
            rungemm<0,0,0,0,0>(g);
        }
        // 4. merged SSM pairs
        ssm_run2(usx, 512, xp_l,  576, dtw_l,  dtb_l,  Al_l,  qiw_l, qib_l, kiw_l, kib_l,
                 true,  yfwd, dbcd, delta, hsum, qbuf, kbuf, attn);
        ssm_run2(ub,  256, xpe_l, 320, dtew_l, dteb_l, Ale_l, qew_l, qeb_l, kew_l, keb_l,
                 false, ybwd, dbcd, delta, hsum, qbuf, kbuf, attn);
        // 5. out_inner: sequential split-K (bias launch + accumulate launch)
        rungemm<0,0,0,0,0>(GA(yfwd,          oiw_l,           oib_l,   cat2, MR, 512, 512, 512, 512, 1024));
        rungemm<0,1,0,0,0>(GA(yfwd + MR*512, oiw_l + 512*512, nullptr, cat2, MR, 512, 512, 512, 512, 1024));
        // out_exit
        rungemm<0,0,0,0,0>(GA(ybwd,          oew_l,           oeb_l,   oe,   MR, 256, 256, 256, 256, 256));
        rungemm<0,1,0,0,0>(GA(ybwd + MR*256, oew_l + 256*256, nullptr, oe,   MR, 256, 256, 256, 256, 256));
        // up: flip fused into A loader
        rungemm<0,0,0,0,1>(GA(oe, upw_l, upb_l, cat2 + 512, MR, 512, 256, 256, 512, 1024));
        // 6. out projection with fused residual (A2 = hs0); layer 1 fuses final silu
        {
            float* dst = (l == 1) ? (float*)d_out : xbuf;
            GArgs g = GA(cat2, ow_l, ob_l, dst, MR, 512, 1024, 1024, 512, 512);
            g.A2 = hs0;
            if (l == 1) rungemm<1,0,1,0,0>(g);
            else        rungemm<0,0,1,0,0>(g);
        }
        cur = xbuf;
    }
}

// round 7
// speedup vs baseline: 1.5861x; 1.5861x over previous
#include <cuda_runtime.h>
#include <math.h>
#include <stdint.h>

#define BATCH 4
#define LSEQ  512
#define DMODEL 512
#define DFF   512
#define DINNER 256
#define MR    (BATCH*LSEQ)   /* 2048 rows */
#define MR2   (2*MR)         /* 4096 rows: merged pair */

// ---------------------------------------------------------------------------
// Scratch: single static device buffer (allocation-free rule). 128 MB.
// ---------------------------------------------------------------------------
__device__ __align__(16) float g_scratch[32u*1024u*1024u];

__device__ __forceinline__ float siluf(float x){ return x / (1.0f + expf(-x)); }
__device__ __forceinline__ float softplusf(float x){ return (x > 20.0f) ? x : log1pf(expf(x)); }

__device__ __forceinline__ uint32_t f2tf32(float x){
    uint32_t r; asm("cvt.rna.tf32.f32 %0, %1;" : "=r"(r) : "f"(x)); return r;
}
__device__ __forceinline__ void mma_tf32(float* c, const uint32_t* a, const uint32_t* b){
    asm volatile("mma.sync.aligned.m16n8k8.row.col.f32.tf32.tf32.f32 "
        "{%0,%1,%2,%3}, {%4,%5,%6,%7}, {%8,%9}, {%0,%1,%2,%3};"
        : "+f"(c[0]),"+f"(c[1]),"+f"(c[2]),"+f"(c[3])
        : "r"(a[0]),"r"(a[1]),"r"(a[2]),"r"(a[3]), "r"(b[0]),"r"(b[1]));
}

// ---------------------------------------------------------------------------
// TF32 tensor-core GEMM (exact round-3 configuration — best known).
// C[M,N] = act(A[M,K](lda) @ W[K,N](ldw) + bias) [+C if ACC]
// 128x64 tile, 256 threads (8 warps, 4x2), warp tile 32x32 (2x4 m16n8k8).
// K-chunk 16, double-buffered smem, 1-chunk register prefetch.
// M%128==0, K%16==0, N arbitrary. Batched via blockIdx.z.
// ---------------------------------------------------------------------------
template<int ACT, int ACC>
__global__ __launch_bounds__(256)
void gemm_tc(const float* __restrict__ A, const float* __restrict__ W,
             const float* __restrict__ bias, float* __restrict__ C,
             int M, int N, int K, int lda, int ldw, int ldc,
             long long Ab, long long Wb, long long Cb)
{
    __shared__ uint32_t As[2][128][20];
    __shared__ uint32_t Bs[2][16][72];
    const int bz = blockIdx.z;
    A += (long long)bz * Ab;  W += (long long)bz * Wb;  C += (long long)bz * Cb;
    const int t = threadIdx.x;
    const int lane = t & 31, wid = t >> 5;
    const int wm = wid >> 1, wn = wid & 1;
    const int gp = lane >> 2, tg = lane & 3;
    const int row0 = blockIdx.y * 128, col0 = blockIdx.x * 64;
    const int a_r = t >> 1, a_k = (t & 1) * 8;
    const int b_k = t >> 4, b_n = (t & 15) * 4;

    float c[2][4][4] = {};
    float4 av0, av1, bv;

    // prefetch chunk 0
    {
        const float* ap = A + (long long)(row0 + a_r) * lda + a_k;
        av0 = *(const float4*)ap; av1 = *(const float4*)(ap + 4);
        int gn = col0 + b_n;
        const float* wp = W + (long long)b_k * ldw + gn;
        if (gn + 3 < N) bv = *(const float4*)wp;
        else {
            bv.x = (gn  <N)?wp[0]:0.f; bv.y = (gn+1<N)?wp[1]:0.f;
            bv.z = (gn+2<N)?wp[2]:0.f; bv.w = (gn+3<N)?wp[3]:0.f;
        }
    }

    int buf = 0;
    for (int kb = 0; kb < K; kb += 16) {
        uint32_t* as = &As[buf][a_r][a_k];
        as[0]=f2tf32(av0.x); as[1]=f2tf32(av0.y); as[2]=f2tf32(av0.z); as[3]=f2tf32(av0.w);
        as[4]=f2tf32(av1.x); as[5]=f2tf32(av1.y); as[6]=f2tf32(av1.z); as[7]=f2tf32(av1.w);
        uint32_t* bs = &Bs[buf][b_k][b_n];
        bs[0]=f2tf32(bv.x); bs[1]=f2tf32(bv.y); bs[2]=f2tf32(bv.z); bs[3]=f2tf32(bv.w);
        __syncthreads();
        if (kb + 16 < K) {
            const float* ap = A + (long long)(row0 + a_r) * lda + (kb + 16) + a_k;
            av0 = *(const float4*)ap; av1 = *(const float4*)(ap + 4);
            int gn = col0 + b_n;
            const float* wp = W + (long long)(kb + 16 + b_k) * ldw + gn;
            if (gn + 3 < N) bv = *(const float4*)wp;
            else {
                bv.x = (gn  <N)?wp[0]:0.f; bv.y = (gn+1<N)?wp[1]:0.f;
                bv.z = (gn+2<N)?wp[2]:0.f; bv.w = (gn+3<N)?wp[3]:0.f;
            }
        }
        #pragma unroll
        for (int ks = 0; ks < 2; ks++) {
            const int k0 = ks * 8;
            uint32_t a[2][4], b[4][2];
            #pragma unroll
            for (int mb = 0; mb < 2; mb++) {
                int r0 = wm*32 + mb*16 + gp;
                a[mb][0] = As[buf][r0  ][k0 + tg];
                a[mb][1] = As[buf][r0+8][k0 + tg];
                a[mb][2] = As[buf][r0  ][k0 + 4 + tg];
                a[mb][3] = As[buf][r0+8][k0 + 4 + tg];
            }
            #pragma unroll
            for (int nb = 0; nb < 4; nb++) {
                int cc = wn*32 + nb*8 + gp;
                b[nb][0] = Bs[buf][k0 + tg    ][cc];
                b[nb][1] = Bs[buf][k0 + 4 + tg][cc];
            }
            #pragma unroll
            for (int mb = 0; mb < 2; mb++)
                #pragma unroll
                for (int nb = 0; nb < 4; nb++)
                    mma_tf32(c[mb][nb], a[mb], b[nb]);
        }
        buf ^= 1;
    }

    #pragma unroll
    for (int mb = 0; mb < 2; mb++) {
        #pragma unroll
        for (int half = 0; half < 2; half++) {
            long long gr = row0 + wm*32 + mb*16 + gp + half*8;
            #pragma unroll
            for (int nb = 0; nb < 4; nb++) {
                #pragma unroll
                for (int j = 0; j < 2; j++) {
                    int gn = col0 + wn*32 + nb*8 + tg*2 + j;
                    if (gn < N) {
                        float v = c[mb][nb][half*2 + j];
                        if (bias) v += bias[gn];
                        if (ACT==2) v = softplusf(v);
                        if (ACC) v += C[gr*ldc + gn];
                        C[gr*ldc + gn] = v;
                    }
                }
            }
        }
    }
}

// ---------------------------------------------------------------------------
// hs0(2048x1024) -> stacked silu / flipped-silu pairs
// ---------------------------------------------------------------------------
__global__ void silu_flip_k(const float* __restrict__ hs0, float* __restrict__ sx,
                            float* __restrict__ sz, float* __restrict__ fx,
                            float* __restrict__ fz)
{
    int i = blockIdx.x*256 + threadIdx.x;
    if (i >= MR*DFF) return;
    int d = i & (DFF-1);
    int m = i >> 9;
    int b = m >> 9, tt = m & (LSEQ-1);
    float s1 = siluf(hs0[m*1024 + d]);
    float s2 = siluf(hs0[m*1024 + 512 + d]);
    sx[i] = s1; sz[i] = s2;
    int mf = (b << 9) + (LSEQ-1 - tt);
    fx[mf*DFF + d] = siluf(s1);
    fz[mf*DFF + d] = siluf(s2);
}

// ---------------------------------------------------------------------------
// Selective scan over nseq sequences of length LSEQ. Thread per (seq,d,n).
// ---------------------------------------------------------------------------
__global__ void scan_k(const float* __restrict__ delta, const float* __restrict__ u,
                       const float* __restrict__ Bm, int ldb,
                       const float* __restrict__ Alog,
                       float* __restrict__ hsum, int D, int nseq)
{
    int tid = blockIdx.x*256 + threadIdx.x;
    int n = tid & 15;
    int seg = tid >> 4;
    int d = seg % D;
    int s = seg / D;
    if (s >= nseq) return;
    float An = -expf(Alog[n]);
    float h = 0.f;
    int base = s * LSEQ;
    #pragma unroll 4
    for (int ts = 0; ts < LSEQ; ts++) {
        int r = base + ts;
        float dl = delta[r*D + d];
        float ul = u[r*D + d];
        float Bv = Bm[(long long)r*ldb + n];
        float a = expf(dl * An);
        h = fmaf(a, h, dl * ul * Bv);
        float v = h;
        v += __shfl_xor_sync(0xffffffffu, v, 1);
        v += __shfl_xor_sync(0xffffffffu, v, 2);
        v += __shfl_xor_sync(0xffffffffu, v, 4);
        v += __shfl_xor_sync(0xffffffffu, v, 8);
        if (n == 0) hsum[r*D + d] = v;
    }
}

// ---------------------------------------------------------------------------
// attn[s,i,j] = softmax_j( dot(q[s,i,:], k[s,j,:]) / 16 ).  Block per (i,s).
// ---------------------------------------------------------------------------
__global__ void attn_k(const float* __restrict__ q, const float* __restrict__ k,
                       float* __restrict__ attn)
{
    const int i = blockIdx.x, s = blockIdx.y;
    __shared__ float qs[16];
    __shared__ float red[16];
    const int t = threadIdx.x;  // 256
    if (t < 16) qs[t] = q[(s*LSEQ + i)*16 + t];
    __syncthreads();
    float v[2];
    #pragma unroll
    for (int jj = 0; jj < 2; jj++) {
        int j = t + jj*256;
        const float4* kr = (const float4*)(k + (long long)(s*LSEQ + j)*16);
        float4 k0 = kr[0], k1 = kr[1], k2 = kr[2], k3 = kr[3];
        float sc = qs[0]*k0.x + qs[1]*k0.y + qs[2]*k0.z + qs[3]*k0.w
                 + qs[4]*k1.x + qs[5]*k1.y + qs[6]*k1.z + qs[7]*k1.w
                 + qs[8]*k2.x + qs[9]*k2.y + qs[10]*k2.z + qs[11]*k2.w
                 + qs[12]*k3.x + qs[13]*k3.y + qs[14]*k3.z + qs[15]*k3.w;
        v[jj] = sc * (1.0f/16.0f);
    }
    float m = fmaxf(v[0], v[1]);
    for (int o=16;o;o>>=1) m = fmaxf(m, __shfl_xor_sync(0xffffffffu, m, o));
    if ((t&31)==0) red[t>>5] = m;
    __syncthreads();
    if (t == 0) { float mm = red[0]; for (int w=1;w<8;w++) mm = fmaxf(mm, red[w]); red[0] = mm; }
    __syncthreads();
    float bm = red[0];
    v[0] = expf(v[0]-bm); v[1] = expf(v[1]-bm);
    float sm = v[0] + v[1];
    for (int o=16;o;o>>=1) sm += __shfl_xor_sync(0xffffffffu, sm, o);
    if ((t&31)==0) red[8 + (t>>5)] = sm;
    __syncthreads();
    if (t == 0) { float ss = 0.f; for (int w=0;w<8;w++) ss += red[8+w]; red[8] = ss; }
    __syncthreads();
    float inv = 1.0f / red[8];
    float* arow = attn + ((long long)s*LSEQ + i)*LSEQ;
    arow[t]     = v[0]*inv;
    arow[t+256] = v[1]*inv;
}

// y[m, d] += Dm[m, d] * u[m, d]  over M2 rows (Dm = dbcd col 64+)
__global__ void addmul_k(float* __restrict__ y, const float* __restrict__ dbcd,
                         int ldp, const float* __restrict__ u, int D, int M2)
{
    int i = blockIdx.x*256 + threadIdx.x;
    if (i >= M2*D) return;
    int m = i / D, d = i - m*D;
    y[i] += dbcd[(long long)m*ldp + 64 + d] * u[i];
}

// dst[b, t, :] = src[b, L-1-t, :]   (2048 rows)
__global__ void flip_k(const float* __restrict__ src, float* __restrict__ dst, int D)
{
    int i = blockIdx.x*256 + threadIdx.x;
    if (i >= MR*D) return;
    int d = i % D; int m = i / D;
    int b = m >> 9, tt = m & (LSEQ-1);
    dst[((b<<9) + (LSEQ-1 - tt))*D + d] = src[i];
}

__global__ void addv_k(float* __restrict__ a, const float* __restrict__ b, int n)
{
    int i = blockIdx.x*256 + threadIdx.x;
    if (i < n) a[i] += b[i];
}

__global__ void silu_out_k(const float* __restrict__ x, float* __restrict__ out, int n)
{
    int i = blockIdx.x*256 + threadIdx.x;
    if (i < n) out[i] = siluf(x[i]);
}

// ---------------------------------------------------------------------------
// Host side
// ---------------------------------------------------------------------------
static inline void gemm(int act, int accf, cudaStream_t st,
                        const float* A, const float* W, const float* bias,
                        float* C, int M, int N, int K, int lda, int ldw, int ldc,
                        int bat = 1, long long Ab = 0, long long Wb = 0, long long Cb = 0)
{
    dim3 g((N + 63) / 64, M / 128, bat), b(256);
    if (accf) {
        gemm_tc<0,1><<<g, b, 0, st>>>(A, W, bias, C, M, N, K, lda, ldw, ldc, Ab, Wb, Cb);
    } else if (act == 0) {
        gemm_tc<0,0><<<g, b, 0, st>>>(A, W, bias, C, M, N, K, lda, ldw, ldc, Ab, Wb, Cb);
    } else {
        gemm_tc<2,0><<<g, b, 0, st>>>(A, W, bias, C, M, N, K, lda, ldw, ldc, Ab, Wb, Cb);
    }
}

// Merged-pair SSM on u [4096 x D], stream + private buffers.
static void ssm_run2(cudaStream_t st, const float* u, int D, const float* projw, int Np,
                     const float* dtw, const float* dtb, const float* Alog,
                     const float* qw, const float* qb, const float* kw, const float* kb,
                     bool useD, float* yout,
                     float* dbcd, float* delta, float* hsum, float* qbuf, float* kbuf,
                     float* attn)
{
    gemm(0, 0, st, u, projw, nullptr, dbcd, MR2, Np, D, D, Np, Np);
    gemm(2, 0, st, dbcd, dtw, dtb, delta, MR2, D, 32, Np, D, D);          // softplus
    scan_k<<<(8*D*16)/256, 256, 0, st>>>(delta, u, dbcd + 32, Np, Alog, hsum, D, 8);
    gemm(2, 0, st, u, qw, qb, qbuf, MR2, 16, D, D, 16, 16);               // softplus
    gemm(2, 0, st, dbcd + 48, kw, kb, kbuf, MR2, 16, 16, Np, 16, 16);     // softplus
    attn_k<<<dim3(LSEQ, 8), 256, 0, st>>>(qbuf, kbuf, attn);
    gemm(0, 0, st, attn, hsum, nullptr, yout, LSEQ, D, LSEQ, LSEQ, D, D,
         8, (long long)LSEQ*LSEQ, (long long)LSEQ*D, (long long)LSEQ*D);
    if (useD) addmul_k<<<(MR2*D)/256, 256, 0, st>>>(yout, dbcd, Np, u, D, MR2);
}

extern "C" void kernel_launch(void* const* d_in, const int* in_sizes, int n_in,
                              void* d_out, int out_size)
{
    (void)in_sizes; (void)n_in; (void)out_size;

    // One-time stream/event creation (first call happens outside graph capture).
    static cudaStream_t s1 = nullptr;
    static cudaEvent_t eFork = nullptr, eJoin = nullptr;
    if (!s1) {
        cudaStreamCreateWithFlags(&s1, cudaStreamNonBlocking);
        cudaEventCreateWithFlags(&eFork, cudaEventDisableTiming);
        cudaEventCreateWithFlags(&eJoin, cudaEventDisableTiming);
    }
    cudaStream_t s0 = 0;

    float* S = nullptr;
    cudaGetSymbolAddress((void**)&S, g_scratch);

    // scratch layout (floats)
    float* hs0    = S;                  // 2048*1024
    float* usx    = hs0    + 2097152;   // [4096 x 512]
    float* ufb    = usx    + 2097152;   // [4096 x 512]
    float* ub     = ufb    + 2097152;   // [4096 x 256]
    float* dbcdF  = ub     + 1048576;   // 4096*576   (forward-chain set)
    float* deltaF = dbcdF  + 2359296;   // 4096*512
    float* hsumF  = deltaF + 2097152;   // 4096*512
    float* qbufF  = hsumF  + 2097152;   // 4096*16
    float* kbufF  = qbufF  + 65536;
    float* attnF  = kbufF  + 65536;     // 8*512*512
    float* dbcdB  = attnF  + 2097152;   // 4096*320   (backward-chain set)
    float* deltaB = dbcdB  + 1310720;   // 4096*256
    float* hsumB  = deltaB + 1048576;   // 4096*256
    float* qbufB  = hsumB  + 1048576;   // 4096*16
    float* kbufB  = qbufB  + 65536;
    float* attnB  = kbufB  + 65536;     // 8*512*512
    float* yfwd   = attnB  + 2097152;   // [4096 x 512]
    float* ybwd   = yfwd   + 2097152;   // [4096 x 256]
    float* cat2   = ybwd   + 1048576;   // 2048*1024
    float* oe     = cat2   + 2097152;   // 2048*256
    float* oef    = oe     + 524288;    // 2048*256
    float* xbuf   = oef    + 524288;    // 2048*512

    const float* x             = (const float*)d_in[0];
    const float* in_w          = (const float*)d_in[1];
    const float* in_b          = (const float*)d_in[2];
    const float* x_proj_w      = (const float*)d_in[3];
    const float* dt_w          = (const float*)d_in[4];
    const float* dt_b          = (const float*)d_in[5];
    const float* A_log         = (const float*)d_in[6];
    const float* exit_x_w      = (const float*)d_in[7];
    const float* exit_x_b      = (const float*)d_in[8];
    const float* exit_z_w      = (const float*)d_in[9];
    const float* exit_z_b      = (const float*)d_in[10];
    const float* x_proj_exit_w = (const float*)d_in[11];
    const float* dt_exit_w     = (const float*)d_in[12];
    const float* dt_exit_b     = (const float*)d_in[13];
    const float* A_log_exit    = (const float*)d_in[14];
    const float* out_inner_w   = (const float*)d_in[15];
    const float* out_inner_b   = (const float*)d_in[16];
    const float* out_exit_w    = (const float*)d_in[17];
    const float* out_exit_b    = (const float*)d_in[18];
    const float* up_w          = (const float*)d_in[19];
    const float* up_b          = (const float*)d_in[20];
    const float* out_w         = (const float*)d_in[21];
    const float* out_b         = (const float*)d_in[22];
    const float* q_in_w        = (const float*)d_in[23];
    const float* q_in_b        = (const float*)d_in[24];
    const float* k_in_w        = (const float*)d_in[25];
    const float* k_in_b        = (const float*)d_in[26];
    const float* q_ex_w        = (const float*)d_in[27];
    const float* q_ex_b        = (const float*)d_in[28];
    const float* k_ex_w        = (const float*)d_in[29];
    const float* k_ex_b        = (const float*)d_in[30];

    const float* cur = x;
    for (int l = 0; l < 2; l++) {
        const float* in_w_l = in_w + (long long)l*512*1024;
        const float* in_b_l = in_b + l*1024;
        const float* xp_l   = x_proj_w + (long long)l*512*576;
        const float* dtw_l  = dt_w + l*32*512;
        const float* dtb_l  = dt_b + l*512;
        const float* Al_l   = A_log + l*16;
        const float* exw_l  = exit_x_w + (long long)l*512*256;
        const float* exb_l  = exit_x_b + l*256;
        const float* ezw_l  = exit_z_w + (long long)l*512*256;
        const float* ezb_l  = exit_z_b + l*256;
        const float* xpe_l  = x_proj_exit_w + (long long)l*256*320;
        const float* dtew_l = dt_exit_w + l*32*256;
        const float* dteb_l = dt_exit_b + l*256;
        const float* Ale_l  = A_log_exit + l*16;
        const float* oiw_l  = out_inner_w + (long long)l*1024*512;
        const float* oib_l  = out_inner_b + l*512;
        const float* oew_l  = out_exit_w + (long long)l*512*256;
        const float* oeb_l  = out_exit_b + l*256;
        const float* upw_l  = up_w + (long long)l*256*512;
        const float* upb_l  = up_b + l*512;
        const float* ow_l   = out_w + (long long)l*1024*512;
        const float* ob_l   = out_b + l*512;
        const float* qiw_l  = q_in_w + l*512*16;
        const float* qib_l  = q_in_b + l*16;
        const float* kiw_l  = k_in_w + l*16*16;
        const float* kib_l  = k_in_b + l*16;
        const float* qew_l  = q_ex_w + l*256*16;
        const float* qeb_l  = q_ex_b + l*16;
        const float* kew_l  = k_ex_w + l*16*16;
        const float* keb_l  = k_ex_b + l*16;

        // ---- serial head: in-proj + activations (stream 0)
        gemm(0, 0, s0, cur, in_w_l, in_b_l, hs0, MR, 1024, 512, 512, 1024, 1024);
        silu_flip_k<<<(MR*DFF)/256, 256, 0, s0>>>(hs0, usx, usx + MR*DFF,
                                                  ufb, ufb + MR*DFF);

        // ---- FORK: backward chain onto s1
        cudaEventRecord(eFork, s0);
        cudaStreamWaitEvent(s1, eFork, 0);

        // s1: exit projections -> backward SSM -> out_exit -> flip -> up
        gemm(0, 0, s1, ufb,          exw_l, exb_l, ub,          MR, 256, 512, 512, 256, 256);
        gemm(0, 0, s1, ufb + MR*DFF, ezw_l, ezb_l, ub + MR*256, MR, 256, 512, 512, 256, 256);
        ssm_run2(s1, ub, 256, xpe_l, 320, dtew_l, dteb_l, Ale_l,
                 qew_l, qeb_l, kew_l, keb_l, false, ybwd,
                 dbcdB, deltaB, hsumB, qbufB, kbufB, attnB);
        gemm(0, 0, s1, ybwd,          oew_l,           oeb_l,   oe, MR, 256, 256, 256, 256, 256);
        gemm(0, 1, s1, ybwd + MR*256, oew_l + 256*256, nullptr, oe, MR, 256, 256, 256, 256, 256);
        flip_k<<<(MR*256)/256, 256, 0, s1>>>(oe, oef, 256);
        gemm(0, 0, s1, oef, upw_l, upb_l, cat2 + 512, MR, 512, 256, 256, 512, 1024);
        cudaEventRecord(eJoin, s1);

        // s0 (concurrent): forward SSM -> out_inner
        ssm_run2(s0, usx, 512, xp_l, 576, dtw_l, dtb_l, Al_l,
                 qiw_l, qib_l, kiw_l, kib_l, true, yfwd,
                 dbcdF, deltaF, hsumF, qbufF, kbufF, attnF);
        gemm(0, 0, s0, yfwd,          oiw_l,           oib_l,   cat2, MR, 512, 512, 512, 512, 1024);
        gemm(0, 1, s0, yfwd + MR*512, oiw_l + 512*512, nullptr, cat2, MR, 512, 512, 512, 512, 1024);

        // ---- JOIN: residual + out projection (stream 0)
        cudaStreamWaitEvent(s0, eJoin, 0);
        addv_k<<<(MR*1024)/256, 256, 0, s0>>>(cat2, hs0, MR*1024);
        gemm(0, 0, s0, cat2, ow_l, ob_l, xbuf, MR, 512, 1024, 1024, 512, 512);
        cur = xbuf;
    }
    silu_out_k<<<(MR*DMODEL)/256, 256, 0, s0>>>(xbuf, (float*)d_out, MR*DMODEL);
}

// round 8
// speedup vs baseline: 1.8809x; 1.1859x over previous
#include <cuda_runtime.h>
#include <math.h>
#include <stdint.h>

#define BATCH 4
#define LSEQ  512
#define DMODEL 512
#define DFF   512
#define DINNER 256
#define MR    (BATCH*LSEQ)   /* 2048 rows */
#define MR2   (2*MR)         /* 4096 rows: merged pair */

__device__ __align__(16) float g_scratch[32u*1024u*1024u];

__device__ __forceinline__ float siluf(float x){ return x / (1.0f + expf(-x)); }
__device__ __forceinline__ float softplusf(float x){ return (x > 20.0f) ? x : log1pf(expf(x)); }

__device__ __forceinline__ uint32_t f2tf32(float x){
    uint32_t r; asm("cvt.rna.tf32.f32 %0, %1;" : "=r"(r) : "f"(x)); return r;
}
__device__ __forceinline__ void mma_tf32(float* c, const uint32_t* a, const uint32_t* b){
    asm volatile("mma.sync.aligned.m16n8k8.row.col.f32.tf32.tf32.f32 "
        "{%0,%1,%2,%3}, {%4,%5,%6,%7}, {%8,%9}, {%0,%1,%2,%3};"
        : "+f"(c[0]),"+f"(c[1]),"+f"(c[2]),"+f"(c[3])
        : "r"(a[0]),"r"(a[1]),"r"(a[2]),"r"(a[3]), "r"(b[0]),"r"(b[1]));
}

// ---------------------------------------------------------------------------
// TF32 tensor-core GEMM (round-3 configuration — proven). Adds only biasb.
// C[M,N] = act(A @ W + bias[bz]) [+C if ACC]; batched via blockIdx.z.
// ---------------------------------------------------------------------------
template<int ACT, int ACC>
__global__ __launch_bounds__(256)
void gemm_tc(const float* __restrict__ A, const float* __restrict__ W,
             const float* __restrict__ bias, float* __restrict__ C,
             int M, int N, int K, int lda, int ldw, int ldc,
             long long Ab, long long Wb, long long Cb, long long biasb)
{
    __shared__ uint32_t As[2][128][20];
    __shared__ uint32_t Bs[2][16][72];
    const int bz = blockIdx.z;
    A += (long long)bz * Ab;  W += (long long)bz * Wb;  C += (long long)bz * Cb;
    const float* biasp = bias ? (bias + (long long)bz * biasb) : nullptr;
    const int t = threadIdx.x;
    const int lane = t & 31, wid = t >> 5;
    const int wm = wid >> 1, wn = wid & 1;
    const int gp = lane >> 2, tg = lane & 3;
    const int row0 = blockIdx.y * 128, col0 = blockIdx.x * 64;
    const int a_r = t >> 1, a_k = (t & 1) * 8;
    const int b_k = t >> 4, b_n = (t & 15) * 4;

    float c[2][4][4] = {};
    float4 av0, av1, bv;

    {
        const float* ap = A + (long long)(row0 + a_r) * lda + a_k;
        av0 = *(const float4*)ap; av1 = *(const float4*)(ap + 4);
        int gn = col0 + b_n;
        const float* wp = W + (long long)b_k * ldw + gn;
        if (gn + 3 < N) bv = *(const float4*)wp;
        else {
            bv.x = (gn  <N)?wp[0]:0.f; bv.y = (gn+1<N)?wp[1]:0.f;
            bv.z = (gn+2<N)?wp[2]:0.f; bv.w = (gn+3<N)?wp[3]:0.f;
        }
    }

    int buf = 0;
    for (int kb = 0; kb < K; kb += 16) {
        uint32_t* as = &As[buf][a_r][a_k];
        as[0]=f2tf32(av0.x); as[1]=f2tf32(av0.y); as[2]=f2tf32(av0.z); as[3]=f2tf32(av0.w);
        as[4]=f2tf32(av1.x); as[5]=f2tf32(av1.y); as[6]=f2tf32(av1.z); as[7]=f2tf32(av1.w);
        uint32_t* bs = &Bs[buf][b_k][b_n];
        bs[0]=f2tf32(bv.x); bs[1]=f2tf32(bv.y); bs[2]=f2tf32(bv.z); bs[3]=f2tf32(bv.w);
        __syncthreads();
        if (kb + 16 < K) {
            const float* ap = A + (long long)(row0 + a_r) * lda + (kb + 16) + a_k;
            av0 = *(const float4*)ap; av1 = *(const float4*)(ap + 4);
            int gn = col0 + b_n;
            const float* wp = W + (long long)(kb + 16 + b_k) * ldw + gn;
            if (gn + 3 < N) bv = *(const float4*)wp;
            else {
                bv.x = (gn  <N)?wp[0]:0.f; bv.y = (gn+1<N)?wp[1]:0.f;
                bv.z = (gn+2<N)?wp[2]:0.f; bv.w = (gn+3<N)?wp[3]:0.f;
            }
        }
        #pragma unroll
        for (int ks = 0; ks < 2; ks++) {
            const int k0 = ks * 8;
            uint32_t a[2][4], b[4][2];
            #pragma unroll
            for (int mb = 0; mb < 2; mb++) {
                int r0 = wm*32 + mb*16 + gp;
                a[mb][0] = As[buf][r0  ][k0 + tg];
                a[mb][1] = As[buf][r0+8][k0 + tg];
                a[mb][2] = As[buf][r0  ][k0 + 4 + tg];
                a[mb][3] = As[buf][r0+8][k0 + 4 + tg];
            }
            #pragma unroll
            for (int nb = 0; nb < 4; nb++) {
                int cc = wn*32 + nb*8 + gp;
                b[nb][0] = Bs[buf][k0 + tg    ][cc];
                b[nb][1] = Bs[buf][k0 + 4 + tg][cc];
            }
            #pragma unroll
            for (int mb = 0; mb < 2; mb++)
                #pragma unroll
                for (int nb = 0; nb < 4; nb++)
                    mma_tf32(c[mb][nb], a[mb], b[nb]);
        }
        buf ^= 1;
    }

    #pragma unroll
    for (int mb = 0; mb < 2; mb++) {
        #pragma unroll
        for (int half = 0; half < 2; half++) {
            long long gr = row0 + wm*32 + mb*16 + gp + half*8;
            #pragma unroll
            for (int nb = 0; nb < 4; nb++) {
                #pragma unroll
                for (int j = 0; j < 2; j++) {
                    int gn = col0 + wn*32 + nb*8 + tg*2 + j;
                    if (gn < N) {
                        float v = c[mb][nb][half*2 + j];
                        if (biasp) v += biasp[gn];
                        if (ACT==2) v = softplusf(v);
                        if (ACC) v += C[gr*ldc + gn];
                        C[gr*ldc + gn] = v;
                    }
                }
            }
        }
    }
}

__global__ void silu_flip_k(const float* __restrict__ hs0, float* __restrict__ sx,
                            float* __restrict__ sz, float* __restrict__ fx,
                            float* __restrict__ fz)
{
    int i = blockIdx.x*256 + threadIdx.x;
    if (i >= MR*DFF) return;
    int d = i & (DFF-1);
    int m = i >> 9;
    int b = m >> 9, tt = m & (LSEQ-1);
    float s1 = siluf(hs0[m*1024 + d]);
    float s2 = siluf(hs0[m*1024 + 512 + d]);
    sx[i] = s1; sz[i] = s2;
    int mf = (b << 9) + (LSEQ-1 - tt);
    fx[mf*DFF + d] = siluf(s1);
    fz[mf*DFF + d] = siluf(s2);
}

__global__ void scan_k(const float* __restrict__ delta, const float* __restrict__ u,
                       const float* __restrict__ Bm, int ldb,
                       const float* __restrict__ Alog,
                       float* __restrict__ hsum, int D, int nseq)
{
    int tid = blockIdx.x*256 + threadIdx.x;
    int n = tid & 15;
    int seg = tid >> 4;
    int d = seg % D;
    int s = seg / D;
    if (s >= nseq) return;
    float An = -expf(Alog[n]);
    float h = 0.f;
    int base = s * LSEQ;
    #pragma unroll 4
    for (int ts = 0; ts < LSEQ; ts++) {
        int r = base + ts;
        float dl = delta[r*D + d];
        float ul = u[r*D + d];
        float Bv = Bm[(long long)r*ldb + n];
        float a = expf(dl * An);
        h = fmaf(a, h, dl * ul * Bv);
        float v = h;
        v += __shfl_xor_sync(0xffffffffu, v, 1);
        v += __shfl_xor_sync(0xffffffffu, v, 2);
        v += __shfl_xor_sync(0xffffffffu, v, 4);
        v += __shfl_xor_sync(0xffffffffu, v, 8);
        if (n == 0) hsum[r*D + d] = v;
    }
}

// Fused skinny projections: q = softplus(u@qw+qb), k = softplus(Cm@kw+kb)
__global__ void qk_k(const float* __restrict__ u, int D,
                     const float* __restrict__ qw, const float* __restrict__ qb,
                     const float* __restrict__ dbcd, int Np,
                     const float* __restrict__ kw, const float* __restrict__ kb,
                     float* __restrict__ qbuf, float* __restrict__ kbuf)
{
    int t = threadIdx.x;
    int c = t & 15, r16 = t >> 4;
    long long row = (long long)blockIdx.x * 16 + r16;
    const float* ar = u + row * D;
    float acc = 0.f;
    #pragma unroll 4
    for (int k = 0; k < D; k += 4) {
        float4 a4 = *(const float4*)(ar + k);
        acc = fmaf(a4.x, qw[(k+0)*16 + c], acc);
        acc = fmaf(a4.y, qw[(k+1)*16 + c], acc);
        acc = fmaf(a4.z, qw[(k+2)*16 + c], acc);
        acc = fmaf(a4.w, qw[(k+3)*16 + c], acc);
    }
    qbuf[row*16 + c] = softplusf(acc + qb[c]);
    const float* cr = dbcd + row * Np + 48;
    float acck = 0.f;
    #pragma unroll
    for (int k = 0; k < 16; k++) acck = fmaf(cr[k], kw[k*16 + c], acck);
    kbuf[row*16 + c] = softplusf(acck + kb[c]);
}

__global__ void attn_k(const float* __restrict__ q, const float* __restrict__ k,
                       float* __restrict__ attn)
{
    const int i = blockIdx.x, s = blockIdx.y;
    __shared__ float qs[16];
    __shared__ float red[16];
    const int t = threadIdx.x;  // 256
    if (t < 16) qs[t] = q[(s*LSEQ + i)*16 + t];
    __syncthreads();
    float v[2];
    #pragma unroll
    for (int jj = 0; jj < 2; jj++) {
        int j = t + jj*256;
        const float4* kr = (const float4*)(k + (long long)(s*LSEQ + j)*16);
        float4 k0 = kr[0], k1 = kr[1], k2 = kr[2], k3 = kr[3];
        float sc = qs[0]*k0.x + qs[1]*k0.y + qs[2]*k0.z + qs[3]*k0.w
                 + qs[4]*k1.x + qs[5]*k1.y + qs[6]*k1.z + qs[7]*k1.w
                 + qs[8]*k2.x + qs[9]*k2.y + qs[10]*k2.z + qs[11]*k2.w
                 + qs[12]*k3.x + qs[13]*k3.y + qs[14]*k3.z + qs[15]*k3.w;
        v[jj] = sc * (1.0f/16.0f);
    }
    float m = fmaxf(v[0], v[1]);
    for (int o=16;o;o>>=1) m = fmaxf(m, __shfl_xor_sync(0xffffffffu, m, o));
    if ((t&31)==0) red[t>>5] = m;
    __syncthreads();
    if (t == 0) { float mm = red[0]; for (int w=1;w<8;w++) mm = fmaxf(mm, red[w]); red[0] = mm; }
    __syncthreads();
    float bm = red[0];
    v[0] = expf(v[0]-bm); v[1] = expf(v[1]-bm);
    float sm = v[0] + v[1];
    for (int o=16;o;o>>=1) sm += __shfl_xor_sync(0xffffffffu, sm, o);
    if ((t&31)==0) red[8 + (t>>5)] = sm;
    __syncthreads();
    if (t == 0) { float ss = 0.f; for (int w=0;w<8;w++) ss += red[8+w]; red[8] = ss; }
    __syncthreads();
    float inv = 1.0f / red[8];
    float* arow = attn + ((long long)s*LSEQ + i)*LSEQ;
    arow[t]     = v[0]*inv;
    arow[t+256] = v[1]*inv;
}

// ycat[m, d] += Dm * u on concat layout: col d<D -> stacked row m; else row m+MR.
__global__ void addmul_cat_k(float* __restrict__ y, const float* __restrict__ dbcd,
                             const float* __restrict__ u, int D, int Np)
{
    int i = blockIdx.x*256 + threadIdx.x;
    if (i >= MR*2*D) return;
    int m = i / (2*D), d = i - m*(2*D);
    int sr = (d < D) ? m : m + MR;
    int pd = (d < D) ? d : d - D;
    y[i] += dbcd[(long long)sr*Np + 64 + pd] * u[(long long)sr*D + pd];
}

__global__ void flip_k(const float* __restrict__ src, float* __restrict__ dst, int D)
{
    int i = blockIdx.x*256 + threadIdx.x;
    if (i >= MR*D) return;
    int d = i % D; int m = i / D;
    int b = m >> 9, tt = m & (LSEQ-1);
    dst[((b<<9) + (LSEQ-1 - tt))*D + d] = src[i];
}

__global__ void addv_k(float* __restrict__ a, const float* __restrict__ b, int n)
{
    int i = blockIdx.x*256 + threadIdx.x;
    if (i < n) a[i] += b[i];
}

__global__ void silu_out_k(const float* __restrict__ x, float* __restrict__ out, int n)
{
    int i = blockIdx.x*256 + threadIdx.x;
    if (i < n) out[i] = siluf(x[i]);
}

// ---------------------------------------------------------------------------
// Host side
// ---------------------------------------------------------------------------
static inline void gemm(int act, int accf, cudaStream_t st,
                        const float* A, const float* W, const float* bias,
                        float* C, int M, int N, int K, int lda, int ldw, int ldc,
                        int bat = 1, long long Ab = 0, long long Wb = 0, long long Cb = 0,
                        long long biasb = 0)
{
    dim3 g((N + 63) / 64, M / 128, bat), b(256);
    if (accf) {
        gemm_tc<0,1><<<g, b, 0, st>>>(A, W, bias, C, M, N, K, lda, ldw, ldc, Ab, Wb, Cb, biasb);
    } else if (act == 0) {
        gemm_tc<0,0><<<g, b, 0, st>>>(A, W, bias, C, M, N, K, lda, ldw, ldc, Ab, Wb, Cb, biasb);
    } else {
        gemm_tc<2,0><<<g, b, 0, st>>>(A, W, bias, C, M, N, K, lda, ldw, ldc, Ab, Wb, Cb, biasb);
    }
}

// Merged-pair SSM writing concat layout ycat[2048 x 2D].
// st = chain stream, side = helper stream (qk+softmax + z-half attn GEMM).
static void ssm_cat(cudaStream_t st, cudaStream_t side,
                    cudaEvent_t eA, cudaEvent_t eScan, cudaEvent_t eAttn, cudaEvent_t eY2,
                    const float* u, int D, const float* projw, int Np,
                    const float* dtw, const float* dtb, const float* Alog,
                    const float* qw, const float* qb, const float* kw, const float* kb,
                    bool useD, float* ycat,
                    float* dbcd, float* delta, float* hsum, float* qbuf, float* kbuf,
                    float* attn)
{
    gemm(0, 0, st, u, projw, nullptr, dbcd, MR2, Np, D, D, Np, Np);
    cudaEventRecord(eA, st);
    gemm(2, 0, st, dbcd, dtw, dtb, delta, MR2, D, 32, Np, D, D);          // softplus
    scan_k<<<(8*D*16)/256, 256, 0, st>>>(delta, u, dbcd + 32, Np, Alog, hsum, D, 8);
    cudaEventRecord(eScan, st);

    // side: q/k + softmax (needs only u + dbcd), then z-half attn GEMM
    cudaStreamWaitEvent(side, eA, 0);
    qk_k<<<MR2/16, 256, 0, side>>>(u, D, qw, qb, dbcd, Np, kw, kb, qbuf, kbuf);
    attn_k<<<dim3(LSEQ, 8), 256, 0, side>>>(qbuf, kbuf, attn);
    cudaEventRecord(eAttn, side);
    cudaStreamWaitEvent(side, eScan, 0);
    gemm(0, 0, side, attn + 4ll*LSEQ*LSEQ, hsum + 4ll*LSEQ*D, nullptr, ycat + D,
         LSEQ, D, LSEQ, LSEQ, D, 2*D,
         4, (long long)LSEQ*LSEQ, (long long)LSEQ*D, (long long)LSEQ*2*D);
    cudaEventRecord(eY2, side);

    // st: x-half attn GEMM
    cudaStreamWaitEvent(st, eAttn, 0);
    gemm(0, 0, st, attn, hsum, nullptr, ycat,
         LSEQ, D, LSEQ, LSEQ, D, 2*D,
         4, (long long)LSEQ*LSEQ, (long long)LSEQ*D, (long long)LSEQ*2*D);
    cudaStreamWaitEvent(st, eY2, 0);
    if (useD) addmul_cat_k<<<(MR*2*D)/256, 256, 0, st>>>(ycat, dbcd, u, D, Np);
}

extern "C" void kernel_launch(void* const* d_in, const int* in_sizes, int n_in,
                              void* d_out, int out_size)
{
    (void)in_sizes; (void)n_in; (void)out_size;

    static cudaStream_t s1 = nullptr, s2 = nullptr, s3 = nullptr;
    static cudaEvent_t ev[12];
    if (!s1) {
        cudaStreamCreateWithFlags(&s1, cudaStreamNonBlocking);
        cudaStreamCreateWithFlags(&s2, cudaStreamNonBlocking);
        cudaStreamCreateWithFlags(&s3, cudaStreamNonBlocking);
        for (int i = 0; i < 12; i++) cudaEventCreateWithFlags(&ev[i], cudaEventDisableTiming);
    }
    cudaStream_t s0 = 0;

    float* S = nullptr;
    cudaGetSymbolAddress((void**)&S, g_scratch);

    float* hs0    = S;                  // 2048*1024
    float* usx    = hs0    + 2097152;   // [4096 x 512]
    float* ufb    = usx    + 2097152;   // [4096 x 512]
    float* ub     = ufb    + 2097152;   // [4096 x 256]
    float* dbcdF  = ub     + 1048576;   // 4096*576
    float* deltaF = dbcdF  + 2359296;   // 4096*512
    float* hsumF  = deltaF + 2097152;   // 4096*512
    float* qbufF  = hsumF  + 2097152;   // 4096*16
    float* kbufF  = qbufF  + 65536;
    float* attnF  = kbufF  + 65536;     // 8*512*512
    float* dbcdB  = attnF  + 2097152;   // 4096*320
    float* deltaB = dbcdB  + 1310720;   // 4096*256
    float* hsumB  = deltaB + 1048576;   // 4096*256
    float* qbufB  = hsumB  + 1048576;   // 4096*16
    float* kbufB  = qbufB  + 65536;
    float* attnB  = kbufB  + 65536;     // 8*512*512
    float* ycatF  = attnB  + 2097152;   // [2048 x 1024]
    float* ybcatB = ycatF  + 2097152;   // [2048 x 512]
    float* cat2   = ybcatB + 1048576;   // 2048*1024
    float* oe     = cat2   + 2097152;   // 2048*256
    float* oef    = oe     + 524288;    // 2048*256
    float* xbuf   = oef    + 524288;    // 2048*512

    const float* x             = (const float*)d_in[0];
    const float* in_w          = (const float*)d_in[1];
    const float* in_b          = (const float*)d_in[2];
    const float* x_proj_w      = (const float*)d_in[3];
    const float* dt_w          = (const float*)d_in[4];
    const float* dt_b          = (const float*)d_in[5];
    const float* A_log         = (const float*)d_in[6];
    const float* exit_x_w      = (const float*)d_in[7];
    const float* exit_x_b      = (const float*)d_in[8];
    const float* exit_z_w      = (const float*)d_in[9];
    const float* exit_z_b      = (const float*)d_in[10];
    const float* x_proj_exit_w = (const float*)d_in[11];
    const float* dt_exit_w     = (const float*)d_in[12];
    const float* dt_exit_b     = (const float*)d_in[13];
    const float* A_log_exit    = (const float*)d_in[14];
    const float* out_inner_w   = (const float*)d_in[15];
    const float* out_inner_b   = (const float*)d_in[16];
    const float* out_exit_w    = (const float*)d_in[17];
    const float* out_exit_b    = (const float*)d_in[18];
    const float* up_w          = (const float*)d_in[19];
    const float* up_b          = (const float*)d_in[20];
    const float* out_w         = (const float*)d_in[21];
    const float* out_b         = (const float*)d_in[22];
    const float* q_in_w        = (const float*)d_in[23];
    const float* q_in_b        = (const float*)d_in[24];
    const float* k_in_w        = (const float*)d_in[25];
    const float* k_in_b        = (const float*)d_in[26];
    const float* q_ex_w        = (const float*)d_in[27];
    const float* q_ex_b        = (const float*)d_in[28];
    const float* k_ex_w        = (const float*)d_in[29];
    const float* k_ex_b        = (const float*)d_in[30];

    const float* cur = x;
    for (int l = 0; l < 2; l++) {
        const float* in_w_l = in_w + (long long)l*512*1024;
        const float* in_b_l = in_b + l*1024;
        const float* xp_l   = x_proj_w + (long long)l*512*576;
        const float* dtw_l  = dt_w + l*32*512;
        const float* dtb_l  = dt_b + l*512;
        const float* Al_l   = A_log + l*16;
        const float* exw_l  = exit_x_w + (long long)l*512*256;
        const float* exb_l  = exit_x_b + l*256;
        const float* ezw_l  = exit_z_w + (long long)l*512*256;
        const float* ezb_l  = exit_z_b + l*256;
        const float* xpe_l  = x_proj_exit_w + (long long)l*256*320;
        const float* dtew_l = dt_exit_w + l*32*256;
        const float* dteb_l = dt_exit_b + l*256;
        const float* Ale_l  = A_log_exit + l*16;
        const float* oiw_l  = out_inner_w + (long long)l*1024*512;
        const float* oib_l  = out_inner_b + l*512;
        const float* oew_l  = out_exit_w + (long long)l*512*256;
        const float* oeb_l  = out_exit_b + l*256;
        const float* upw_l  = up_w + (long long)l*256*512;
        const float* upb_l  = up_b + l*512;
        const float* ow_l   = out_w + (long long)l*1024*512;
        const float* ob_l   = out_b + l*512;
        const float* qiw_l  = q_in_w + l*512*16;
        const float* qib_l  = q_in_b + l*16;
        const float* kiw_l  = k_in_w + l*16*16;
        const float* kib_l  = k_in_b + l*16;
        const float* qew_l  = q_ex_w + l*256*16;
        const float* qeb_l  = q_ex_b + l*16;
        const float* kew_l  = k_ex_w + l*16*16;
        const float* keb_l  = k_ex_b + l*16;

        // ---- serial head
        gemm(0, 0, s0, cur, in_w_l, in_b_l, hs0, MR, 1024, 512, 512, 1024, 1024);
        silu_flip_k<<<(MR*DFF)/256, 256, 0, s0>>>(hs0, usx, usx + MR*DFF,
                                                  ufb, ufb + MR*DFF);

        // ---- FORK backward chain onto s1
        cudaEventRecord(ev[8], s0);
        cudaStreamWaitEvent(s1, ev[8], 0);

        // s1: batched exit projections (bias stride across the two weight sets)
        gemm(0, 0, s1, ufb, exw_l, exb_l, ub, MR, 256, 512, 512, 256, 256,
             2, (long long)MR*512, (long long)(ezw_l - exw_l), (long long)MR*256,
             (long long)(ezb_l - exb_l));
        ssm_cat(s1, s3, ev[4], ev[5], ev[6], ev[7],
                ub, 256, xpe_l, 320, dtew_l, dteb_l, Ale_l,
                qew_l, qeb_l, kew_l, keb_l, false, ybcatB,
                dbcdB, deltaB, hsumB, qbufB, kbufB, attnB);
        // out_exit as single K=512 GEMM on the concat buffer
        gemm(0, 0, s1, ybcatB, oew_l, oeb_l, oe, MR, 256, 512, 512, 256, 256);
        flip_k<<<(MR*256)/256, 256, 0, s1>>>(oe, oef, 256);
        gemm(0, 0, s1, oef, upw_l, upb_l, cat2 + 512, MR, 512, 256, 256, 512, 1024);
        cudaEventRecord(ev[9], s1);

        // s0 (concurrent): forward SSM + out_inner (single K=1024 GEMM)
        ssm_cat(s0, s2, ev[0], ev[1], ev[2], ev[3],
                usx, 512, xp_l, 576, dtw_l, dtb_l, Al_l,
                qiw_l, qib_l, kiw_l, kib_l, true, ycatF,
                dbcdF, deltaF, hsumF, qbufF, kbufF, attnF);
        gemm(0, 0, s0, ycatF, oiw_l, oib_l, cat2, MR, 512, 1024, 1024, 512, 1024);

        // ---- JOIN
        cudaStreamWaitEvent(s0, ev[9], 0);
        addv_k<<<(MR*1024)/256, 256, 0, s0>>>(cat2, hs0, MR*1024);
        gemm(0, 0, s0, cat2, ow_l, ob_l, xbuf, MR, 512, 1024, 1024, 512, 512);
        cur = xbuf;
    }
    silu_out_k<<<(MR*DMODEL)/256, 256, 0, s0>>>(xbuf, (float*)d_out, MR*DMODEL);
}

// round 11
// speedup vs baseline: 1.9053x; 1.0130x over previous
#include <cuda_runtime.h>
#include <math.h>
#include <stdint.h>

#define BATCH 4
#define LSEQ  512
#define DMODEL 512
#define DFF   512
#define DINNER 256
#define MR    (BATCH*LSEQ)   /* 2048 rows */
#define MR2   (2*MR)         /* 4096 rows: merged pair */

#define GEMM_SMEM_WORDS (2*128*36 + 2*32*72)
#define GEMM_SMEM_BYTES (GEMM_SMEM_WORDS * 4)   /* 55296 */

__device__ __align__(16) float g_scratch[32u*1024u*1024u];

__device__ __forceinline__ float siluf(float x){ return x / (1.0f + expf(-x)); }
__device__ __forceinline__ float softplusf(float x){ return (x > 20.0f) ? x : log1pf(expf(x)); }

__device__ __forceinline__ uint32_t f2tf32(float x){
    uint32_t r; asm("cvt.rna.tf32.f32 %0, %1;" : "=r"(r) : "f"(x)); return r;
}
__device__ __forceinline__ void mma_tf32(float* c, const uint32_t* a, const uint32_t* b){
    asm volatile("mma.sync.aligned.m16n8k8.row.col.f32.tf32.tf32.f32 "
        "{%0,%1,%2,%3}, {%4,%5,%6,%7}, {%8,%9}, {%0,%1,%2,%3};"
        : "+f"(c[0]),"+f"(c[1]),"+f"(c[2]),"+f"(c[3])
        : "r"(a[0]),"r"(a[1]),"r"(a[2]),"r"(a[3]), "r"(b[0]),"r"(b[1]));
}

// ---------------------------------------------------------------------------
// TF32 tensor-core GEMM. K-chunk 32, double-buffered DYNAMIC smem (55 KB),
// 1-chunk-deep prefetch in named scalar registers.
//   C = act((A [+A2 if FA2]) @ W + bias[bz])
// 128x64 tile, 256 threads (8 warps 4x2), warp tile 32x32 (2x4 m16n8k8).
// REQUIRES: M%128==0, K%32==0, N%64==0. Batched via blockIdx.z.
// ---------------------------------------------------------------------------
template<int ACT, int FA2>
__global__ __launch_bounds__(256)
void gemm_tc(const float* __restrict__ A, const float* __restrict__ A2,
             const float* __restrict__ W,
             const float* __restrict__ bias, float* __restrict__ C,
             int M, int N, int K, int lda, int ldw, int ldc,
             long long Ab, long long Wb, long long Cb, long long biasb)
{
    extern __shared__ uint32_t dynsmem[];
    uint32_t (*As)[128][36] = (uint32_t(*)[128][36])dynsmem;             // stride 36: conflict-free
    uint32_t (*Bs)[32][72]  = (uint32_t(*)[32][72])(dynsmem + 2*128*36); // stride 72: conflict-free

    const int bz = blockIdx.z;
    A += (long long)bz * Ab;  W += (long long)bz * Wb;  C += (long long)bz * Cb;
    const float* biasp = bias ? (bias + (long long)bz * biasb) : nullptr;
    const int t = threadIdx.x;
    const int lane = t & 31, wid = t >> 5;
    const int wm = wid >> 1, wn = wid & 1;
    const int gp = lane >> 2, tg = lane & 3;
    const int row0 = blockIdx.y * 128, col0 = blockIdx.x * 64;
    const int a_r = t >> 1, a_k = (t & 1) * 16;   // A: 16 floats (4 x float4)
    const int b_k = t >> 3, b_n = (t & 7) * 8;    // W: 8 floats (2 x float4)

    const float* Arow  = A + (long long)(row0 + a_r) * lda;
    const float* A2row = FA2 ? (A2 + (long long)bz * Ab + (long long)(row0 + a_r) * lda)
                             : nullptr;

    float c[2][4][4] = {};
    float4 av0, av1, av2, av3, bv0, bv1;

    // prefetch chunk 0
    {
        const float* ap = Arow + a_k;
        av0 = *(const float4*)(ap);   av1 = *(const float4*)(ap + 4);
        av2 = *(const float4*)(ap+8); av3 = *(const float4*)(ap + 12);
        if (FA2) {
            const float* a2 = A2row + a_k;
            float4 b0=*(const float4*)a2, b1=*(const float4*)(a2+4),
                   b2=*(const float4*)(a2+8), b3=*(const float4*)(a2+12);
            av0.x+=b0.x; av0.y+=b0.y; av0.z+=b0.z; av0.w+=b0.w;
            av1.x+=b1.x; av1.y+=b1.y; av1.z+=b1.z; av1.w+=b1.w;
            av2.x+=b2.x; av2.y+=b2.y; av2.z+=b2.z; av2.w+=b2.w;
            av3.x+=b3.x; av3.y+=b3.y; av3.z+=b3.z; av3.w+=b3.w;
        }
        const float* wp = W + (long long)b_k * ldw + col0 + b_n;
        bv0 = *(const float4*)wp; bv1 = *(const float4*)(wp + 4);
    }

    int buf = 0;
    for (int kb = 0; kb < K; kb += 32) {
        {
            uint32_t* as = &As[buf][a_r][a_k];
            as[0] =f2tf32(av0.x); as[1] =f2tf32(av0.y); as[2] =f2tf32(av0.z); as[3] =f2tf32(av0.w);
            as[4] =f2tf32(av1.x); as[5] =f2tf32(av1.y); as[6] =f2tf32(av1.z); as[7] =f2tf32(av1.w);
            as[8] =f2tf32(av2.x); as[9] =f2tf32(av2.y); as[10]=f2tf32(av2.z); as[11]=f2tf32(av2.w);
            as[12]=f2tf32(av3.x); as[13]=f2tf32(av3.y); as[14]=f2tf32(av3.z); as[15]=f2tf32(av3.w);
            uint32_t* bs = &Bs[buf][b_k][b_n];
            bs[0]=f2tf32(bv0.x); bs[1]=f2tf32(bv0.y); bs[2]=f2tf32(bv0.z); bs[3]=f2tf32(bv0.w);
            bs[4]=f2tf32(bv1.x); bs[5]=f2tf32(bv1.y); bs[6]=f2tf32(bv1.z); bs[7]=f2tf32(bv1.w);
        }
        __syncthreads();
        if (kb + 32 < K) {
            const float* ap = Arow + (kb + 32) + a_k;
            av0 = *(const float4*)(ap);   av1 = *(const float4*)(ap + 4);
            av2 = *(const float4*)(ap+8); av3 = *(const float4*)(ap + 12);
            if (FA2) {
                const float* a2 = A2row + (kb + 32) + a_k;
                float4 b0=*(const float4*)a2, b1=*(const float4*)(a2+4),
                       b2=*(const float4*)(a2+8), b3=*(const float4*)(a2+12);
                av0.x+=b0.x; av0.y+=b0.y; av0.z+=b0.z; av0.w+=b0.w;
                av1.x+=b1.x; av1.y+=b1.y; av1.z+=b1.z; av1.w+=b1.w;
                av2.x+=b2.x; av2.y+=b2.y; av2.z+=b2.z; av2.w+=b2.w;
                av3.x+=b3.x; av3.y+=b3.y; av3.z+=b3.z; av3.w+=b3.w;
            }
            const float* wp = W + (long long)(kb + 32 + b_k) * ldw + col0 + b_n;
            bv0 = *(const float4*)wp; bv1 = *(const float4*)(wp + 4);
        }
        #pragma unroll
        for (int ks = 0; ks < 4; ks++) {
            const int k0 = ks * 8;
            uint32_t a[2][4], b[4][2];
            #pragma unroll
            for (int mb = 0; mb < 2; mb++) {
                int r0 = wm*32 + mb*16 + gp;
                a[mb][0] = As[buf][r0  ][k0 + tg];
                a[mb][1] = As[buf][r0+8][k0 + tg];
                a[mb][2] = As[buf][r0  ][k0 + 4 + tg];
                a[mb][3] = As[buf][r0+8][k0 + 4 + tg];
            }
            #pragma unroll
            for (int nb = 0; nb < 4; nb++) {
                int cc = wn*32 + nb*8 + gp;
                b[nb][0] = Bs[buf][k0 + tg    ][cc];
                b[nb][1] = Bs[buf][k0 + 4 + tg][cc];
            }
            #pragma unroll
            for (int mb = 0; mb < 2; mb++)
                #pragma unroll
                for (int nb = 0; nb < 4; nb++)
                    mma_tf32(c[mb][nb], a[mb], b[nb]);
        }
        buf ^= 1;
    }

    #pragma unroll
    for (int mb = 0; mb < 2; mb++) {
        #pragma unroll
        for (int half = 0; half < 2; half++) {
            long long gr = row0 + wm*32 + mb*16 + gp + half*8;
            #pragma unroll
            for (int nb = 0; nb < 4; nb++) {
                #pragma unroll
                for (int j = 0; j < 2; j++) {
                    int gn = col0 + wn*32 + nb*8 + tg*2 + j;
                    float v = c[mb][nb][half*2 + j];
                    if (biasp) v += biasp[gn];
                    if (ACT==1) v = siluf(v);
                    if (ACT==2) v = softplusf(v);
                    C[gr*ldc + gn] = v;
                }
            }
        }
    }
}

__global__ void silu_flip_k(const float* __restrict__ hs0, float* __restrict__ sx,
                            float* __restrict__ sz, float* __restrict__ fx,
                            float* __restrict__ fz)
{
    int i = blockIdx.x*256 + threadIdx.x;
    if (i >= MR*DFF) return;
    int d = i & (DFF-1);
    int m = i >> 9;
    int b = m >> 9, tt = m & (LSEQ-1);
    float s1 = siluf(hs0[m*1024 + d]);
    float s2 = siluf(hs0[m*1024 + 512 + d]);
    sx[i] = s1; sz[i] = s2;
    int mf = (b << 9) + (LSEQ-1 - tt);
    fx[mf*DFF + d] = siluf(s1);
    fz[mf*DFF + d] = siluf(s2);
}

__global__ void scan_k(const float* __restrict__ delta, const float* __restrict__ u,
                       const float* __restrict__ Bm, int ldb,
                       const float* __restrict__ Alog,
                       float* __restrict__ hsum, int D, int nseq)
{
    int tid = blockIdx.x*256 + threadIdx.x;
    int n = tid & 15;
    int seg = tid >> 4;
    int d = seg % D;
    int s = seg / D;
    if (s >= nseq) return;
    float An = -expf(Alog[n]);
    float h = 0.f;
    int base = s * LSEQ;
    #pragma unroll 4
    for (int ts = 0; ts < LSEQ; ts++) {
        int r = base + ts;
        float dl = delta[r*D + d];
        float ul = u[r*D + d];
        float Bv = Bm[(long long)r*ldb + n];
        float a = expf(dl * An);
        h = fmaf(a, h, dl * ul * Bv);
        float v = h;
        v += __shfl_xor_sync(0xffffffffu, v, 1);
        v += __shfl_xor_sync(0xffffffffu, v, 2);
        v += __shfl_xor_sync(0xffffffffu, v, 4);
        v += __shfl_xor_sync(0xffffffffu, v, 8);
        if (n == 0) hsum[r*D + d] = v;
    }
}

__global__ void qk_k(const float* __restrict__ u, int D,
                     const float* __restrict__ qw, const float* __restrict__ qb,
                     const float* __restrict__ dbcd, int Np,
                     const float* __restrict__ kw, const float* __restrict__ kb,
                     float* __restrict__ qbuf, float* __restrict__ kbuf)
{
    int t = threadIdx.x;
    int c = t & 15, r16 = t >> 4;
    long long row = (long long)blockIdx.x * 16 + r16;
    const float* ar = u + row * D;
    float acc = 0.f;
    #pragma unroll 4
    for (int k = 0; k < D; k += 4) {
        float4 a4 = *(const float4*)(ar + k);
        acc = fmaf(a4.x, qw[(k+0)*16 + c], acc);
        acc = fmaf(a4.y, qw[(k+1)*16 + c], acc);
        acc = fmaf(a4.z, qw[(k+2)*16 + c], acc);
        acc = fmaf(a4.w, qw[(k+3)*16 + c], acc);
    }
    qbuf[row*16 + c] = softplusf(acc + qb[c]);
    const float* cr = dbcd + row * Np + 48;
    float acck = 0.f;
    #pragma unroll
    for (int k = 0; k < 16; k++) acck = fmaf(cr[k], kw[k*16 + c], acck);
    kbuf[row*16 + c] = softplusf(acck + kb[c]);
}

__global__ void attn_k(const float* __restrict__ q, const float* __restrict__ k,
                       float* __restrict__ attn)
{
    const int i = blockIdx.x, s = blockIdx.y;
    __shared__ float qs[16];
    __shared__ float red[16];
    const int t = threadIdx.x;  // 256
    if (t < 16) qs[t] = q[(s*LSEQ + i)*16 + t];
    __syncthreads();
    float v[2];
    #pragma unroll
    for (int jj = 0; jj < 2; jj++) {
        int j = t + jj*256;
        const float4* kr = (const float4*)(k + (long long)(s*LSEQ + j)*16);
        float4 k0 = kr[0], k1 = kr[1], k2 = kr[2], k3 = kr[3];
        float sc = qs[0]*k0.x + qs[1]*k0.y + qs[2]*k0.z + qs[3]*k0.w
                 + qs[4]*k1.x + qs[5]*k1.y + qs[6]*k1.z + qs[7]*k1.w
                 + qs[8]*k2.x + qs[9]*k2.y + qs[10]*k2.z + qs[11]*k2.w
                 + qs[12]*k3.x + qs[13]*k3.y + qs[14]*k3.z + qs[15]*k3.w;
        v[jj] = sc * (1.0f/16.0f);
    }
    float m = fmaxf(v[0], v[1]);
    for (int o=16;o;o>>=1) m = fmaxf(m, __shfl_xor_sync(0xffffffffu, m, o));
    if ((t&31)==0) red[t>>5] = m;
    __syncthreads();
    if (t == 0) { float mm = red[0]; for (int w=1;w<8;w++) mm = fmaxf(mm, red[w]); red[0] = mm; }
    __syncthreads();
    float bm = red[0];
    v[0] = expf(v[0]-bm); v[1] = expf(v[1]-bm);
    float sm = v[0] + v[1];
    for (int o=16;o;o>>=1) sm += __shfl_xor_sync(0xffffffffu, sm, o);
    if ((t&31)==0) red[8 + (t>>5)] = sm;
    __syncthreads();
    if (t == 0) { float ss = 0.f; for (int w=0;w<8;w++) ss += red[8+w]; red[8] = ss; }
    __syncthreads();
    float inv = 1.0f / red[8];
    float* arow = attn + ((long long)s*LSEQ + i)*LSEQ;
    arow[t]     = v[0]*inv;
    arow[t+256] = v[1]*inv;
}

__global__ void addmul_cat_k(float* __restrict__ y, const float* __restrict__ dbcd,
                             const float* __restrict__ u, int D, int Np)
{
    int i = blockIdx.x*256 + threadIdx.x;
    if (i >= MR*2*D) return;
    int m = i / (2*D), d = i - m*(2*D);
    int sr = (d < D) ? m : m + MR;
    int pd = (d < D) ? d : d - D;
    y[i] += dbcd[(long long)sr*Np + 64 + pd] * u[(long long)sr*D + pd];
}

__global__ void flip_k(const float* __restrict__ src, float* __restrict__ dst, int D)
{
    int i = blockIdx.x*256 + threadIdx.x;
    if (i >= MR*D) return;
    int d = i % D; int m = i / D;
    int b = m >> 9, tt = m & (LSEQ-1);
    dst[((b<<9) + (LSEQ-1 - tt))*D + d] = src[i];
}

// ---------------------------------------------------------------------------
// Host side
// ---------------------------------------------------------------------------
static inline void gemm(int act, int fa2, cudaStream_t st,
                        const float* A, const float* A2, const float* W, const float* bias,
                        float* C, int M, int N, int K, int lda, int ldw, int ldc,
                        int bat = 1, long long Ab = 0, long long Wb = 0, long long Cb = 0,
                        long long biasb = 0)
{
    dim3 g(N / 64, M / 128, bat), b(256);
    if (fa2) {
        if (act == 1) gemm_tc<1,1><<<g, b, GEMM_SMEM_BYTES, st>>>(A, A2, W, bias, C, M, N, K, lda, ldw, ldc, Ab, Wb, Cb, biasb);
        else          gemm_tc<0,1><<<g, b, GEMM_SMEM_BYTES, st>>>(A, A2, W, bias, C, M, N, K, lda, ldw, ldc, Ab, Wb, Cb, biasb);
    } else if (act == 0) {
        gemm_tc<0,0><<<g, b, GEMM_SMEM_BYTES, st>>>(A, A2, W, bias, C, M, N, K, lda, ldw, ldc, Ab, Wb, Cb, biasb);
    } else {
        gemm_tc<2,0><<<g, b, GEMM_SMEM_BYTES, st>>>(A, A2, W, bias, C, M, N, K, lda, ldw, ldc, Ab, Wb, Cb, biasb);
    }
}

// Merged-pair SSM writing concat layout ycat[2048 x 2D].
static void ssm_cat(cudaStream_t st, cudaStream_t side,
                    cudaEvent_t eA, cudaEvent_t eScan, cudaEvent_t eAttn, cudaEvent_t eY2,
                    const float* u, int D, const float* projw, int Np,
                    const float* dtw, const float* dtb, const float* Alog,
                    const float* qw, const float* qb, const float* kw, const float* kb,
                    bool useD, float* ycat,
                    float* dbcd, float* delta, float* hsum, float* qbuf, float* kbuf,
                    float* attn)
{
    gemm(0, 0, st, u, nullptr, projw, nullptr, dbcd, MR2, Np, D, D, Np, Np);
    cudaEventRecord(eA, st);
    gemm(2, 0, st, dbcd, nullptr, dtw, dtb, delta, MR2, D, 32, Np, D, D);   // softplus
    scan_k<<<(8*D*16)/256, 256, 0, st>>>(delta, u, dbcd + 32, Np, Alog, hsum, D, 8);
    cudaEventRecord(eScan, st);

    cudaStreamWaitEvent(side, eA, 0);
    qk_k<<<MR2/16, 256, 0, side>>>(u, D, qw, qb, dbcd, Np, kw, kb, qbuf, kbuf);
    attn_k<<<dim3(LSEQ, 8), 256, 0, side>>>(qbuf, kbuf, attn);
    cudaEventRecord(eAttn, side);
    cudaStreamWaitEvent(side, eScan, 0);
    gemm(0, 0, side, attn + 4ll*LSEQ*LSEQ, nullptr, hsum + 4ll*LSEQ*D, nullptr, ycat + D,
         LSEQ, D, LSEQ, LSEQ, D, 2*D,
         4, (long long)LSEQ*LSEQ, (long long)LSEQ*D, (long long)LSEQ*2*D);
    cudaEventRecord(eY2, side);

    cudaStreamWaitEvent(st, eAttn, 0);
    gemm(0, 0, st, attn, nullptr, hsum, nullptr, ycat,
         LSEQ, D, LSEQ, LSEQ, D, 2*D,
         4, (long long)LSEQ*LSEQ, (long long)LSEQ*D, (long long)LSEQ*2*D);
    cudaStreamWaitEvent(st, eY2, 0);
    if (useD) addmul_cat_k<<<(MR*2*D)/256, 256, 0, st>>>(ycat, dbcd, u, D, Np);
}

extern "C" void kernel_launch(void* const* d_in, const int* in_sizes, int n_in,
                              void* d_out, int out_size)
{
    (void)in_sizes; (void)n_in; (void)out_size;

    static cudaStream_t s1 = nullptr, s2 = nullptr, s3 = nullptr;
    static cudaEvent_t ev[12];
    if (!s1) {
        cudaStreamCreateWithFlags(&s1, cudaStreamNonBlocking);
        cudaStreamCreateWithFlags(&s2, cudaStreamNonBlocking);
        cudaStreamCreateWithFlags(&s3, cudaStreamNonBlocking);
        for (int i = 0; i < 12; i++) cudaEventCreateWithFlags(&ev[i], cudaEventDisableTiming);
        cudaFuncSetAttribute(gemm_tc<0,0>, cudaFuncAttributeMaxDynamicSharedMemorySize, GEMM_SMEM_BYTES);
        cudaFuncSetAttribute(gemm_tc<2,0>, cudaFuncAttributeMaxDynamicSharedMemorySize, GEMM_SMEM_BYTES);
        cudaFuncSetAttribute(gemm_tc<0,1>, cudaFuncAttributeMaxDynamicSharedMemorySize, GEMM_SMEM_BYTES);
        cudaFuncSetAttribute(gemm_tc<1,1>, cudaFuncAttributeMaxDynamicSharedMemorySize, GEMM_SMEM_BYTES);
    }
    cudaStream_t s0 = 0;

    float* S = nullptr;
    cudaGetSymbolAddress((void**)&S, g_scratch);

    float* hs0    = S;                  // 2048*1024
    float* usx    = hs0    + 2097152;   // [4096 x 512]
    float* ufb    = usx    + 2097152;   // [4096 x 512]
    float* ub     = ufb    + 2097152;   // [4096 x 256]
    float* dbcdF  = ub     + 1048576;   // 4096*576
    float* deltaF = dbcdF  + 2359296;   // 4096*512
    float* hsumF  = deltaF + 2097152;   // 4096*512
    float* qbufF  = hsumF  + 2097152;   // 4096*16
    float* kbufF  = qbufF  + 65536;
    float* attnF  = kbufF  + 65536;     // 8*512*512
    float* dbcdB  = attnF  + 2097152;   // 4096*320
    float* deltaB = dbcdB  + 1310720;   // 4096*256
    float* hsumB  = deltaB + 1048576;   // 4096*256
    float* qbufB  = hsumB  + 1048576;   // 4096*16
    float* kbufB  = qbufB  + 65536;
    float* attnB  = kbufB  + 65536;     // 8*512*512
    float* ycatF  = attnB  + 2097152;   // [2048 x 1024]
    float* ybcatB = ycatF  + 2097152;   // [2048 x 512]
    float* cat2   = ybcatB + 1048576;   // 2048*1024
    float* oe     = cat2   + 2097152;   // 2048*256
    float* oef    = oe     + 524288;    // 2048*256
    float* xbuf   = oef    + 524288;    // 2048*512

    const float* x             = (const float*)d_in[0];
    const float* in_w          = (const float*)d_in[1];
    const float* in_b          = (const float*)d_in[2];
    const float* x_proj_w      = (const float*)d_in[3];
    const float* dt_w          = (const float*)d_in[4];
    const float* dt_b          = (const float*)d_in[5];
    const float* A_log         = (const float*)d_in[6];
    const float* exit_x_w      = (const float*)d_in[7];
    const float* exit_x_b      = (const float*)d_in[8];
    const float* exit_z_w      = (const float*)d_in[9];
    const float* exit_z_b      = (const float*)d_in[10];
    const float* x_proj_exit_w = (const float*)d_in[11];
    const float* dt_exit_w     = (const float*)d_in[12];
    const float* dt_exit_b     = (const float*)d_in[13];
    const float* A_log_exit    = (const float*)d_in[14];
    const float* out_inner_w   = (const float*)d_in[15];
    const float* out_inner_b   = (const float*)d_in[16];
    const float* out_exit_w    = (const float*)d_in[17];
    const float* out_exit_b    = (const float*)d_in[18];
    const float* up_w          = (const float*)d_in[19];
    const float* up_b          = (const float*)d_in[20];
    const float* out_w         = (const float*)d_in[21];
    const float* out_b         = (const float*)d_in[22];
    const float* q_in_w        = (const float*)d_in[23];
    const float* q_in_b        = (const float*)d_in[24];
    const float* k_in_w        = (const float*)d_in[25];
    const float* k_in_b        = (const float*)d_in[26];
    const float* q_ex_w        = (const float*)d_in[27];
    const float* q_ex_b        = (const float*)d_in[28];
    const float* k_ex_w        = (const float*)d_in[29];
    const float* k_ex_b        = (const float*)d_in[30];

    const float* cur = x;
    for (int l = 0; l < 2; l++) {
        const float* in_w_l = in_w + (long long)l*512*1024;
        const float* in_b_l = in_b + l*1024;
        const float* xp_l   = x_proj_w + (long long)l*512*576;
        const float* dtw_l  = dt_w + l*32*512;
        const float* dtb_l  = dt_b + l*512;
        const float* Al_l   = A_log + l*16;
        const float* exw_l  = exit_x_w + (long long)l*512*256;
        const float* exb_l  = exit_x_b + l*256;
        const float* ezw_l  = exit_z_w + (long long)l*512*256;
        const float* ezb_l  = exit_z_b + l*256;
        const float* xpe_l  = x_proj_exit_w + (long long)l*256*320;
        const float* dtew_l = dt_exit_w + l*32*256;
        const float* dteb_l = dt_exit_b + l*256;
        const float* Ale_l  = A_log_exit + l*16;
        const float* oiw_l  = out_inner_w + (long long)l*1024*512;
        const float* oib_l  = out_inner_b + l*512;
        const float* oew_l  = out_exit_w + (long long)l*512*256;
        const float* oeb_l  = out_exit_b + l*256;
        const float* upw_l  = up_w + (long long)l*256*512;
        const float* upb_l  = up_b + l*512;
        const float* ow_l   = out_w + (long long)l*1024*512;
        const float* ob_l   = out_b + l*512;
        const float* qiw_l  = q_in_w + l*512*16;
        const float* qib_l  = q_in_b + l*16;
        const float* kiw_l  = k_in_w + l*16*16;
        const float* kib_l  = k_in_b + l*16;
        const float* qew_l  = q_ex_w + l*256*16;
        const float* qeb_l  = q_ex_b + l*16;
        const float* kew_l  = k_ex_w + l*16*16;
        const float* keb_l  = k_ex_b + l*16;

        // ---- serial head
        gemm(0, 0, s0, cur, nullptr, in_w_l, in_b_l, hs0, MR, 1024, 512, 512, 1024, 1024);
        silu_flip_k<<<(MR*DFF)/256, 256, 0, s0>>>(hs0, usx, usx + MR*DFF,
                                                  ufb, ufb + MR*DFF);

        // ---- FORK backward chain onto s1
        cudaEventRecord(ev[8], s0);
        cudaStreamWaitEvent(s1, ev[8], 0);

        gemm(0, 0, s1, ufb, nullptr, exw_l, exb_l, ub, MR, 256, 512, 512, 256, 256,
             2, (long long)MR*512, (long long)(ezw_l - exw_l), (long long)MR*256,
             (long long)(ezb_l - exb_l));
        ssm_cat(s1, s3, ev[4], ev[5], ev[6], ev[7],
                ub, 256, xpe_l, 320, dtew_l, dteb_l, Ale_l,
                qew_l, qeb_l, kew_l, keb_l, false, ybcatB,
                dbcdB, deltaB, hsumB, qbufB, kbufB, attnB);
        gemm(0, 0, s1, ybcatB, nullptr, oew_l, oeb_l, oe, MR, 256, 512, 512, 256, 256);
        flip_k<<<(MR*256)/256, 256, 0, s1>>>(oe, oef, 256);
        gemm(0, 0, s1, oef, nullptr, upw_l, upb_l, cat2 + 512, MR, 512, 256, 256, 512, 1024);
        cudaEventRecord(ev[9], s1);

        // s0 (concurrent): forward SSM + out_inner
        ssm_cat(s0, s2, ev[0], ev[1], ev[2], ev[3],
                usx, 512, xp_l, 576, dtw_l, dtb_l, Al_l,
                qiw_l, qib_l, kiw_l, kib_l, true, ycatF,
                dbcdF, deltaF, hsumF, qbufF, kbufF, attnF);
        gemm(0, 0, s0, ycatF, nullptr, oiw_l, oib_l, cat2, MR, 512, 1024, 1024, 512, 1024);

        // ---- JOIN: out projection with fused residual (A2 = hs0);
        //      layer 1 fuses final silu and writes d_out directly.
        cudaStreamWaitEvent(s0, ev[9], 0);
        {
            float* dst = (l == 1) ? (float*)d_out : xbuf;
            gemm((l == 1) ? 1 : 0, 1, s0, cat2, hs0, ow_l, ob_l, dst,
                 MR, 512, 1024, 1024, 512, 512);
        }
        cur = xbuf;
    }
}

// round 12
// speedup vs baseline: 1.9495x; 1.0232x over previous
#include <cuda_runtime.h>
#include <math.h>
#include <stdint.h>

#define BATCH 4
#define LSEQ  512
#define DMODEL 512
#define DFF   512
#define DINNER 256
#define MR    (BATCH*LSEQ)   /* 2048 rows */
#define MR2   (2*MR)         /* 4096 rows: merged pair */

__device__ __align__(16) float g_scratch[32u*1024u*1024u];

__device__ __forceinline__ float siluf(float x){ return x / (1.0f + expf(-x)); }
__device__ __forceinline__ float softplusf(float x){ return (x > 20.0f) ? x : log1pf(expf(x)); }

__device__ __forceinline__ uint32_t f2tf32(float x){
    uint32_t r; asm("cvt.rna.tf32.f32 %0, %1;" : "=r"(r) : "f"(x)); return r;
}
__device__ __forceinline__ void mma_tf32(float* c, const uint32_t* a, const uint32_t* b){
    asm volatile("mma.sync.aligned.m16n8k8.row.col.f32.tf32.tf32.f32 "
        "{%0,%1,%2,%3}, {%4,%5,%6,%7}, {%8,%9}, {%0,%1,%2,%3};"
        : "+f"(c[0]),"+f"(c[1]),"+f"(c[2]),"+f"(c[3])
        : "r"(a[0]),"r"(a[1]),"r"(a[2]),"r"(a[3]), "r"(b[0]),"r"(b[1]));
}

// ---------------------------------------------------------------------------
// TF32 tensor-core GEMM, 64x64 tile / 128 threads for multi-CTA/SM residency.
//   C = act((A [+A2 if FA2]) @ W + bias[bz])
// 4 warps (2x2), warp tile 32x32 (2x4 m16n8k8) — round-3 inner loop verbatim.
// K-chunk 16, double-buffered static smem (19 KB), 1-chunk named-reg prefetch.
// REQUIRES: M%64==0, K%16==0, N%64==0. Batched via blockIdx.z.
// ---------------------------------------------------------------------------
template<int ACT, int FA2>
__global__ __launch_bounds__(128)
void gemm_tc(const float* __restrict__ A, const float* __restrict__ A2,
             const float* __restrict__ W,
             const float* __restrict__ bias, float* __restrict__ C,
             int M, int N, int K, int lda, int ldw, int ldc,
             long long Ab, long long Wb, long long Cb, long long biasb)
{
    __shared__ uint32_t As[2][64][20];   // [row][k], stride 20: conflict-free (proven)
    __shared__ uint32_t Bs[2][16][72];   // [k][n],  stride 72: conflict-free (proven)
    const int bz = blockIdx.z;
    A += (long long)bz * Ab;  W += (long long)bz * Wb;  C += (long long)bz * Cb;
    const float* biasp = bias ? (bias + (long long)bz * biasb) : nullptr;
    const int t = threadIdx.x;            // 0..127
    const int lane = t & 31, wid = t >> 5; // 4 warps
    const int wm = wid >> 1, wn = wid & 1; // 2x2 warp grid, 32x32 each
    const int gp = lane >> 2, tg = lane & 3;
    const int row0 = blockIdx.y * 64, col0 = blockIdx.x * 64;
    const int a_r = t >> 1, a_k = (t & 1) * 8;   // A: 8 floats (2 x float4) per thread
    const int b_k = t >> 4, b_n = (t & 15) * 4;  // W: rows b_k and b_k+8, 4 floats each

    const float* Arow  = A + (long long)(row0 + a_r) * lda;
    const float* A2row = FA2 ? (A2 + (long long)bz * Ab + (long long)(row0 + a_r) * lda)
                             : nullptr;

    float c[2][4][4] = {};
    float4 av0, av1, bv0, bv1;

    // prefetch chunk 0
    {
        const float* ap = Arow + a_k;
        av0 = *(const float4*)ap; av1 = *(const float4*)(ap + 4);
        if (FA2) {
            const float* a2 = A2row + a_k;
            float4 b0 = *(const float4*)a2, b1 = *(const float4*)(a2 + 4);
            av0.x+=b0.x; av0.y+=b0.y; av0.z+=b0.z; av0.w+=b0.w;
            av1.x+=b1.x; av1.y+=b1.y; av1.z+=b1.z; av1.w+=b1.w;
        }
        const float* wp = W + (long long)b_k * ldw + col0 + b_n;
        bv0 = *(const float4*)wp;
        bv1 = *(const float4*)(wp + 8ll * ldw);
    }

    int buf = 0;
    for (int kb = 0; kb < K; kb += 16) {
        {
            uint32_t* as = &As[buf][a_r][a_k];
            as[0]=f2tf32(av0.x); as[1]=f2tf32(av0.y); as[2]=f2tf32(av0.z); as[3]=f2tf32(av0.w);
            as[4]=f2tf32(av1.x); as[5]=f2tf32(av1.y); as[6]=f2tf32(av1.z); as[7]=f2tf32(av1.w);
            uint32_t* bs0 = &Bs[buf][b_k][b_n];
            bs0[0]=f2tf32(bv0.x); bs0[1]=f2tf32(bv0.y); bs0[2]=f2tf32(bv0.z); bs0[3]=f2tf32(bv0.w);
            uint32_t* bs1 = &Bs[buf][b_k + 8][b_n];
            bs1[0]=f2tf32(bv1.x); bs1[1]=f2tf32(bv1.y); bs1[2]=f2tf32(bv1.z); bs1[3]=f2tf32(bv1.w);
        }
        __syncthreads();
        if (kb + 16 < K) {
            const float* ap = Arow + (kb + 16) + a_k;
            av0 = *(const float4*)ap; av1 = *(const float4*)(ap + 4);
            if (FA2) {
                const float* a2 = A2row + (kb + 16) + a_k;
                float4 b0 = *(const float4*)a2, b1 = *(const float4*)(a2 + 4);
                av0.x+=b0.x; av0.y+=b0.y; av0.z+=b0.z; av0.w+=b0.w;
                av1.x+=b1.x; av1.y+=b1.y; av1.z+=b1.z; av1.w+=b1.w;
            }
            const float* wp = W + (long long)(kb + 16 + b_k) * ldw + col0 + b_n;
            bv0 = *(const float4*)wp;
            bv1 = *(const float4*)(wp + 8ll * ldw);
        }
        #pragma unroll
        for (int ks = 0; ks < 2; ks++) {
            const int k0 = ks * 8;
            uint32_t a[2][4], b[4][2];
            #pragma unroll
            for (int mb = 0; mb < 2; mb++) {
                int r0 = wm*32 + mb*16 + gp;
                a[mb][0] = As[buf][r0  ][k0 + tg];
                a[mb][1] = As[buf][r0+8][k0 + tg];
                a[mb][2] = As[buf][r0  ][k0 + 4 + tg];
                a[mb][3] = As[buf][r0+8][k0 + 4 + tg];
            }
            #pragma unroll
            for (int nb = 0; nb < 4; nb++) {
                int cc = wn*32 + nb*8 + gp;
                b[nb][0] = Bs[buf][k0 + tg    ][cc];
                b[nb][1] = Bs[buf][k0 + 4 + tg][cc];
            }
            #pragma unroll
            for (int mb = 0; mb < 2; mb++)
                #pragma unroll
                for (int nb = 0; nb < 4; nb++)
                    mma_tf32(c[mb][nb], a[mb], b[nb]);
        }
        buf ^= 1;
    }

    #pragma unroll
    for (int mb = 0; mb < 2; mb++) {
        #pragma unroll
        for (int half = 0; half < 2; half++) {
            long long gr = row0 + wm*32 + mb*16 + gp + half*8;
            #pragma unroll
            for (int nb = 0; nb < 4; nb++) {
                #pragma unroll
                for (int j = 0; j < 2; j++) {
                    int gn = col0 + wn*32 + nb*8 + tg*2 + j;
                    float v = c[mb][nb][half*2 + j];
                    if (biasp) v += biasp[gn];
                    if (ACT==1) v = siluf(v);
                    if (ACT==2) v = softplusf(v);
                    C[gr*ldc + gn] = v;
                }
            }
        }
    }
}

__global__ void silu_flip_k(const float* __restrict__ hs0, float* __restrict__ sx,
                            float* __restrict__ sz, float* __restrict__ fx,
                            float* __restrict__ fz)
{
    int i = blockIdx.x*256 + threadIdx.x;
    if (i >= MR*DFF) return;
    int d = i & (DFF-1);
    int m = i >> 9;
    int b = m >> 9, tt = m & (LSEQ-1);
    float s1 = siluf(hs0[m*1024 + d]);
    float s2 = siluf(hs0[m*1024 + 512 + d]);
    sx[i] = s1; sz[i] = s2;
    int mf = (b << 9) + (LSEQ-1 - tt);
    fx[mf*DFF + d] = siluf(s1);
    fz[mf*DFF + d] = siluf(s2);
}

__global__ void scan_k(const float* __restrict__ delta, const float* __restrict__ u,
                       const float* __restrict__ Bm, int ldb,
                       const float* __restrict__ Alog,
                       float* __restrict__ hsum, int D, int nseq)
{
    int tid = blockIdx.x*256 + threadIdx.x;
    int n = tid & 15;
    int seg = tid >> 4;
    int d = seg % D;
    int s = seg / D;
    if (s >= nseq) return;
    float An = -expf(Alog[n]);
    float h = 0.f;
    int base = s * LSEQ;
    #pragma unroll 4
    for (int ts = 0; ts < LSEQ; ts++) {
        int r = base + ts;
        float dl = delta[r*D + d];
        float ul = u[r*D + d];
        float Bv = Bm[(long long)r*ldb + n];
        float a = expf(dl * An);
        h = fmaf(a, h, dl * ul * Bv);
        float v = h;
        v += __shfl_xor_sync(0xffffffffu, v, 1);
        v += __shfl_xor_sync(0xffffffffu, v, 2);
        v += __shfl_xor_sync(0xffffffffu, v, 4);
        v += __shfl_xor_sync(0xffffffffu, v, 8);
        if (n == 0) hsum[r*D + d] = v;
    }
}

__global__ void qk_k(const float* __restrict__ u, int D,
                     const float* __restrict__ qw, const float* __restrict__ qb,
                     const float* __restrict__ dbcd, int Np,
                     const float* __restrict__ kw, const float* __restrict__ kb,
                     float* __restrict__ qbuf, float* __restrict__ kbuf)
{
    int t = threadIdx.x;
    int c = t & 15, r16 = t >> 4;
    long long row = (long long)blockIdx.x * 16 + r16;
    const float* ar = u + row * D;
    float acc = 0.f;
    #pragma unroll 4
    for (int k = 0; k < D; k += 4) {
        float4 a4 = *(const float4*)(ar + k);
        acc = fmaf(a4.x, qw[(k+0)*16 + c], acc);
        acc = fmaf(a4.y, qw[(k+1)*16 + c], acc);
        acc = fmaf(a4.z, qw[(k+2)*16 + c], acc);
        acc = fmaf(a4.w, qw[(k+3)*16 + c], acc);
    }
    qbuf[row*16 + c] = softplusf(acc + qb[c]);
    const float* cr = dbcd + row * Np + 48;
    float acck = 0.f;
    #pragma unroll
    for (int k = 0; k < 16; k++) acck = fmaf(cr[k], kw[k*16 + c], acck);
    kbuf[row*16 + c] = softplusf(acck + kb[c]);
}

__global__ void attn_k(const float* __restrict__ q, const float* __restrict__ k,
                       float* __restrict__ attn)
{
    const int i = blockIdx.x, s = blockIdx.y;
    __shared__ float qs[16];
    __shared__ float red[16];
    const int t = threadIdx.x;  // 256
    if (t < 16) qs[t] = q[(s*LSEQ + i)*16 + t];
    __syncthreads();
    float v[2];
    #pragma unroll
    for (int jj = 0; jj < 2; jj++) {
        int j = t + jj*256;
        const float4* kr = (const float4*)(k + (long long)(s*LSEQ + j)*16);
        float4 k0 = kr[0], k1 = kr[1], k2 = kr[2], k3 = kr[3];
        float sc = qs[0]*k0.x + qs[1]*k0.y + qs[2]*k0.z + qs[3]*k0.w
                 + qs[4]*k1.x + qs[5]*k1.y + qs[6]*k1.z + qs[7]*k1.w
                 + qs[8]*k2.x + qs[9]*k2.y + qs[10]*k2.z + qs[11]*k2.w
                 + qs[12]*k3.x + qs[13]*k3.y + qs[14]*k3.z + qs[15]*k3.w;
        v[jj] = sc * (1.0f/16.0f);
    }
    float m = fmaxf(v[0], v[1]);
    for (int o=16;o;o>>=1) m = fmaxf(m, __shfl_xor_sync(0xffffffffu, m, o));
    if ((t&31)==0) red[t>>5] = m;
    __syncthreads();
    if (t == 0) { float mm = red[0]; for (int w=1;w<8;w++) mm = fmaxf(mm, red[w]); red[0] = mm; }
    __syncthreads();
    float bm = red[0];
    v[0] = expf(v[0]-bm); v[1] = expf(v[1]-bm);
    float sm = v[0] + v[1];
    for (int o=16;o;o>>=1) sm += __shfl_xor_sync(0xffffffffu, sm, o);
    if ((t&31)==0) red[8 + (t>>5)] = sm;
    __syncthreads();
    if (t == 0) { float ss = 0.f; for (int w=0;w<8;w++) ss += red[8+w]; red[8] = ss; }
    __syncthreads();
    float inv = 1.0f / red[8];
    float* arow = attn + ((long long)s*LSEQ + i)*LSEQ;
    arow[t]     = v[0]*inv;
    arow[t+256] = v[1]*inv;
}

__global__ void addmul_cat_k(float* __restrict__ y, const float* __restrict__ dbcd,
                             const float* __restrict__ u, int D, int Np)
{
    int i = blockIdx.x*256 + threadIdx.x;
    if (i >= MR*2*D) return;
    int m = i / (2*D), d = i - m*(2*D);
    int sr = (d < D) ? m : m + MR;
    int pd = (d < D) ? d : d - D;
    y[i] += dbcd[(long long)sr*Np + 64 + pd] * u[(long long)sr*D + pd];
}

__global__ void flip_k(const float* __restrict__ src, float* __restrict__ dst, int D)
{
    int i = blockIdx.x*256 + threadIdx.x;
    if (i >= MR*D) return;
    int d = i % D; int m = i / D;
    int b = m >> 9, tt = m & (LSEQ-1);
    dst[((b<<9) + (LSEQ-1 - tt))*D + d] = src[i];
}

// ---------------------------------------------------------------------------
// Host side
// ---------------------------------------------------------------------------
static inline void gemm(int act, int fa2, cudaStream_t st,
                        const float* A, const float* A2, const float* W, const float* bias,
                        float* C, int M, int N, int K, int lda, int ldw, int ldc,
                        int bat = 1, long long Ab = 0, long long Wb = 0, long long Cb = 0,
                        long long biasb = 0)
{
    dim3 g(N / 64, M / 64, bat), b(128);
    if (fa2) {
        if (act == 1) gemm_tc<1,1><<<g, b, 0, st>>>(A, A2, W, bias, C, M, N, K, lda, ldw, ldc, Ab, Wb, Cb, biasb);
        else          gemm_tc<0,1><<<g, b, 0, st>>>(A, A2, W, bias, C, M, N, K, lda, ldw, ldc, Ab, Wb, Cb, biasb);
    } else if (act == 0) {
        gemm_tc<0,0><<<g, b, 0, st>>>(A, A2, W, bias, C, M, N, K, lda, ldw, ldc, Ab, Wb, Cb, biasb);
    } else {
        gemm_tc<2,0><<<g, b, 0, st>>>(A, A2, W, bias, C, M, N, K, lda, ldw, ldc, Ab, Wb, Cb, biasb);
    }
}

// Merged-pair SSM writing concat layout ycat[2048 x 2D].
static void ssm_cat(cudaStream_t st, cudaStream_t side,
                    cudaEvent_t eA, cudaEvent_t eScan, cudaEvent_t eAttn, cudaEvent_t eY2,
                    const float* u, int D, const float* projw, int Np,
                    const float* dtw, const float* dtb, const float* Alog,
                    const float* qw, const float* qb, const float* kw, const float* kb,
                    bool useD, float* ycat,
                    float* dbcd, float* delta, float* hsum, float* qbuf, float* kbuf,
                    float* attn)
{
    gemm(0, 0, st, u, nullptr, projw, nullptr, dbcd, MR2, Np, D, D, Np, Np);
    cudaEventRecord(eA, st);
    gemm(2, 0, st, dbcd, nullptr, dtw, dtb, delta, MR2, D, 32, Np, D, D);   // softplus
    scan_k<<<(8*D*16)/256, 256, 0, st>>>(delta, u, dbcd + 32, Np, Alog, hsum, D, 8);
    cudaEventRecord(eScan, st);

    cudaStreamWaitEvent(side, eA, 0);
    qk_k<<<MR2/16, 256, 0, side>>>(u, D, qw, qb, dbcd, Np, kw, kb, qbuf, kbuf);
    attn_k<<<dim3(LSEQ, 8), 256, 0, side>>>(qbuf, kbuf, attn);
    cudaEventRecord(eAttn, side);
    cudaStreamWaitEvent(side, eScan, 0);
    gemm(0, 0, side, attn + 4ll*LSEQ*LSEQ, nullptr, hsum + 4ll*LSEQ*D, nullptr, ycat + D,
         LSEQ, D, LSEQ, LSEQ, D, 2*D,
         4, (long long)LSEQ*LSEQ, (long long)LSEQ*D, (long long)LSEQ*2*D);
    cudaEventRecord(eY2, side);

    cudaStreamWaitEvent(st, eAttn, 0);
    gemm(0, 0, st, attn, nullptr, hsum, nullptr, ycat,
         LSEQ, D, LSEQ, LSEQ, D, 2*D,
         4, (long long)LSEQ*LSEQ, (long long)LSEQ*D, (long long)LSEQ*2*D);
    cudaStreamWaitEvent(st, eY2, 0);
    if (useD) addmul_cat_k<<<(MR*2*D)/256, 256, 0, st>>>(ycat, dbcd, u, D, Np);
}

extern "C" void kernel_launch(void* const* d_in, const int* in_sizes, int n_in,
                              void* d_out, int out_size)
{
    (void)in_sizes; (void)n_in; (void)out_size;

    static cudaStream_t s1 = nullptr, s2 = nullptr, s3 = nullptr;
    static cudaEvent_t ev[12];
    if (!s1) {
        cudaStreamCreateWithFlags(&s1, cudaStreamNonBlocking);
        cudaStreamCreateWithFlags(&s2, cudaStreamNonBlocking);
        cudaStreamCreateWithFlags(&s3, cudaStreamNonBlocking);
        for (int i = 0; i < 12; i++) cudaEventCreateWithFlags(&ev[i], cudaEventDisableTiming);
    }
    cudaStream_t s0 = 0;

    float* S = nullptr;
    cudaGetSymbolAddress((void**)&S, g_scratch);

    float* hs0    = S;                  // 2048*1024
    float* usx    = hs0    + 2097152;   // [4096 x 512]
    float* ufb    = usx    + 2097152;   // [4096 x 512]
    float* ub     = ufb    + 2097152;   // [4096 x 256]
    float* dbcdF  = ub     + 1048576;   // 4096*576
    float* deltaF = dbcdF  + 2359296;   // 4096*512
    float* hsumF  = deltaF + 2097152;   // 4096*512
    float* qbufF  = hsumF  + 2097152;   // 4096*16
    float* kbufF  = qbufF  + 65536;
    float* attnF  = kbufF  + 65536;     // 8*512*512
    float* dbcdB  = attnF  + 2097152;   // 4096*320
    float* deltaB = dbcdB  + 1310720;   // 4096*256
    float* hsumB  = deltaB + 1048576;   // 4096*256
    float* qbufB  = hsumB  + 1048576;   // 4096*16
    float* kbufB  = qbufB  + 65536;
    float* attnB  = kbufB  + 65536;     // 8*512*512
    float* ycatF  = attnB  + 2097152;   // [2048 x 1024]
    float* ybcatB = ycatF  + 2097152;   // [2048 x 512]
    float* cat2   = ybcatB + 1048576;   // 2048*1024
    float* oe     = cat2   + 2097152;   // 2048*256
    float* oef    = oe     + 524288;    // 2048*256
    float* xbuf   = oef    + 524288;    // 2048*512

    const float* x             = (const float*)d_in[0];
    const float* in_w          = (const float*)d_in[1];
    const float* in_b          = (const float*)d_in[2];
    const float* x_proj_w      = (const float*)d_in[3];
    const float* dt_w          = (const float*)d_in[4];
    const float* dt_b          = (const float*)d_in[5];
    const float* A_log         = (const float*)d_in[6];
    const float* exit_x_w      = (const float*)d_in[7];
    const float* exit_x_b      = (const float*)d_in[8];
    const float* exit_z_w      = (const float*)d_in[9];
    const float* exit_z_b      = (const float*)d_in[10];
    const float* x_proj_exit_w = (const float*)d_in[11];
    const float* dt_exit_w     = (const float*)d_in[12];
    const float* dt_exit_b     = (const float*)d_in[13];
    const float* A_log_exit    = (const float*)d_in[14];
    const float* out_inner_w   = (const float*)d_in[15];
    const float* out_inner_b   = (const float*)d_in[16];
    const float* out_exit_w    = (const float*)d_in[17];
    const float* out_exit_b    = (const float*)d_in[18];
    const float* up_w          = (const float*)d_in[19];
    const float* up_b          = (const float*)d_in[20];
    const float* out_w         = (const float*)d_in[21];
    const float* out_b         = (const float*)d_in[22];
    const float* q_in_w        = (const float*)d_in[23];
    const float* q_in_b        = (const float*)d_in[24];
    const float* k_in_w        = (const float*)d_in[25];
    const float* k_in_b        = (const float*)d_in[26];
    const float* q_ex_w        = (const float*)d_in[27];
    const float* q_ex_b        = (const float*)d_in[28];
    const float* k_ex_w        = (const float*)d_in[29];
    const float* k_ex_b        = (const float*)d_in[30];

    const float* cur = x;
    for (int l = 0; l < 2; l++) {
        const float* in_w_l = in_w + (long long)l*512*1024;
        const float* in_b_l = in_b + l*1024;
        const float* xp_l   = x_proj_w + (long long)l*512*576;
        const float* dtw_l  = dt_w + l*32*512;
        const float* dtb_l  = dt_b + l*512;
        const float* Al_l   = A_log + l*16;
        const float* exw_l  = exit_x_w + (long long)l*512*256;
        const float* exb_l  = exit_x_b + l*256;
        const float* ezw_l  = exit_z_w + (long long)l*512*256;
        const float* ezb_l  = exit_z_b + l*256;
        const float* xpe_l  = x_proj_exit_w + (long long)l*256*320;
        const float* dtew_l = dt_exit_w + l*32*256;
        const float* dteb_l = dt_exit_b + l*256;
        const float* Ale_l  = A_log_exit + l*16;
        const float* oiw_l  = out_inner_w + (long long)l*1024*512;
        const float* oib_l  = out_inner_b + l*512;
        const float* oew_l  = out_exit_w + (long long)l*512*256;
        const float* oeb_l  = out_exit_b + l*256;
        const float* upw_l  = up_w + (long long)l*256*512;
        const float* upb_l  = up_b + l*512;
        const float* ow_l   = out_w + (long long)l*1024*512;
        const float* ob_l   = out_b + l*512;
        const float* qiw_l  = q_in_w + l*512*16;
        const float* qib_l  = q_in_b + l*16;
        const float* kiw_l  = k_in_w + l*16*16;
        const float* kib_l  = k_in_b + l*16;
        const float* qew_l  = q_ex_w + l*256*16;
        const float* qeb_l  = q_ex_b + l*16;
        const float* kew_l  = k_ex_w + l*16*16;
        const float* keb_l  = k_ex_b + l*16;

        // ---- serial head
        gemm(0, 0, s0, cur, nullptr, in_w_l, in_b_l, hs0, MR, 1024, 512, 512, 1024, 1024);
        silu_flip_k<<<(MR*DFF)/256, 256, 0, s0>>>(hs0, usx, usx + MR*DFF,
                                                  ufb, ufb + MR*DFF);

        // ---- FORK backward chain onto s1
        cudaEventRecord(ev[8], s0);
        cudaStreamWaitEvent(s1, ev[8], 0);

        gemm(0, 0, s1, ufb, nullptr, exw_l, exb_l, ub, MR, 256, 512, 512, 256, 256,
             2, (long long)MR*512, (long long)(ezw_l - exw_l), (long long)MR*256,
             (long long)(ezb_l - exb_l));
        ssm_cat(s1, s3, ev[4], ev[5], ev[6], ev[7],
                ub, 256, xpe_l, 320, dtew_l, dteb_l, Ale_l,
                qew_l, qeb_l, kew_l, keb_l, false, ybcatB,
                dbcdB, deltaB, hsumB, qbufB, kbufB, attnB);
        gemm(0, 0, s1, ybcatB, nullptr, oew_l, oeb_l, oe, MR, 256, 512, 512, 256, 256);
        flip_k<<<(MR*256)/256, 256, 0, s1>>>(oe, oef, 256);
        gemm(0, 0, s1, oef, nullptr, upw_l, upb_l, cat2 + 512, MR, 512, 256, 256, 512, 1024);
        cudaEventRecord(ev[9], s1);

        // s0 (concurrent): forward SSM + out_inner
        ssm_cat(s0, s2, ev[0], ev[1], ev[2], ev[3],
                usx, 512, xp_l, 576, dtw_l, dtb_l, Al_l,
                qiw_l, qib_l, kiw_l, kib_l, true, ycatF,
                dbcdF, deltaF, hsumF, qbufF, kbufF, attnF);
        gemm(0, 0, s0, ycatF, nullptr, oiw_l, oib_l, cat2, MR, 512, 1024, 1024, 512, 1024);

        // ---- JOIN: out projection with fused residual (A2 = hs0);
        //      layer 1 fuses final silu and writes d_out directly.
        cudaStreamWaitEvent(s0, ev[9], 0);
        {
            float* dst = (l == 1) ? (float*)d_out : xbuf;
            gemm((l == 1) ? 1 : 0, 1, s0, cat2, hs0, ow_l, ob_l, dst,
                 MR, 512, 1024, 1024, 512, 512);
        }
        cur = xbuf;
    }
}

// round 13
// speedup vs baseline: 2.0236x; 1.0380x over previous
#include <cuda_runtime.h>
#include <math.h>
#include <stdint.h>

#define BATCH 4
#define LSEQ  512
#define DMODEL 512
#define DFF   512
#define DINNER 256
#define MR    (BATCH*LSEQ)   /* 2048 rows */
#define MR2   (2*MR)         /* 4096 rows: merged pair */
#define NSTAGE 4

__device__ __align__(16) float g_scratch[32u*1024u*1024u];

__device__ __forceinline__ float siluf(float x){ return x / (1.0f + expf(-x)); }
__device__ __forceinline__ float softplusf(float x){ return (x > 20.0f) ? x : log1pf(expf(x)); }

__device__ __forceinline__ uint32_t f2tf32(float x){
    uint32_t r; asm("cvt.rna.tf32.f32 %0, %1;" : "=r"(r) : "f"(x)); return r;
}
__device__ __forceinline__ uint32_t cvt_tf(uint32_t v){
    return f2tf32(__uint_as_float(v));
}
__device__ __forceinline__ void mma_tf32(float* c, const uint32_t* a, const uint32_t* b){
    asm volatile("mma.sync.aligned.m16n8k8.row.col.f32.tf32.tf32.f32 "
        "{%0,%1,%2,%3}, {%4,%5,%6,%7}, {%8,%9}, {%0,%1,%2,%3};"
        : "+f"(c[0]),"+f"(c[1]),"+f"(c[2]),"+f"(c[3])
        : "r"(a[0]),"r"(a[1]),"r"(a[2]),"r"(a[3]), "r"(b[0]),"r"(b[1]));
}
__device__ __forceinline__ void cp16(uint32_t smem, const void* g){
    asm volatile("cp.async.ca.shared.global [%0], [%1], 16;" :: "r"(smem), "l"(g));
}
#define CP_COMMIT() asm volatile("cp.async.commit_group;" ::: "memory")
#define CP_WAIT(n)  asm volatile("cp.async.wait_group %0;" :: "n"(n) : "memory")

// ---------------------------------------------------------------------------
// TF32 tensor-core GEMM, 64x64 tile / 128 threads.
//   FA2=0: 4-stage cp.async pipeline (smem holds fp32; cvt at fragment load).
//   FA2=1: round-12 register-prefetch path with fused A+A2 loader.
//   C = act((A [+A2 if FA2]) @ W + bias[bz])
// 4 warps (2x2), warp tile 32x32 (2x4 m16n8k8).
// REQUIRES: M%64==0, K%16==0, N%64==0. Batched via blockIdx.z.
// ---------------------------------------------------------------------------
template<int ACT, int FA2>
__global__ __launch_bounds__(128)
void gemm_tc(const float* __restrict__ A, const float* __restrict__ A2,
             const float* __restrict__ W,
             const float* __restrict__ bias, float* __restrict__ C,
             int M, int N, int K, int lda, int ldw, int ldc,
             long long Ab, long long Wb, long long Cb, long long biasb)
{
    __shared__ uint32_t As[NSTAGE][64][20];   // [row][k], stride 20: conflict-free
    __shared__ uint32_t Bs[NSTAGE][16][72];   // [k][n],  stride 72: conflict-free
    const int bz = blockIdx.z;
    A += (long long)bz * Ab;  W += (long long)bz * Wb;  C += (long long)bz * Cb;
    const float* biasp = bias ? (bias + (long long)bz * biasb) : nullptr;
    const int t = threadIdx.x;             // 0..127
    const int lane = t & 31, wid = t >> 5;
    const int wm = wid >> 1, wn = wid & 1;
    const int gp = lane >> 2, tg = lane & 3;
    const int row0 = blockIdx.y * 64, col0 = blockIdx.x * 64;
    const int a_r = t >> 1, a_k = (t & 1) * 8;
    const int b_k = t >> 4, b_n = (t & 15) * 4;

    const float* Arow = A + (long long)(row0 + a_r) * lda;
    float c[2][4][4] = {};

    if (!FA2) {
        // ------------------ cp.async pipelined path ------------------
        const int nc = K >> 4;
        const uint32_t asA = (uint32_t)__cvta_generic_to_shared(&As[0][a_r][a_k]);
        const uint32_t bsB = (uint32_t)__cvta_generic_to_shared(&Bs[0][b_k][b_n]);
        const uint32_t aStride = 64*20*4, bStride = 16*72*4;

        #pragma unroll
        for (int s = 0; s < NSTAGE-1; s++) {
            if (s < nc) {
                const float* ap = Arow + s*16 + a_k;
                cp16(asA + s*aStride,       ap);
                cp16(asA + s*aStride + 16,  ap + 4);
                const float* wp = W + (long long)(s*16 + b_k) * ldw + col0 + b_n;
                cp16(bsB + s*bStride,            wp);
                cp16(bsB + s*bStride + 8*72*4,   wp + 8ll*ldw);
            }
            CP_COMMIT();
        }

        for (int i = 0; i < nc; i++) {
            CP_WAIT(NSTAGE-2);
            __syncthreads();
            {
                int nxt = i + NSTAGE - 1;
                if (nxt < nc) {
                    int s = nxt & (NSTAGE-1);
                    const float* ap = Arow + nxt*16 + a_k;
                    cp16(asA + s*aStride,       ap);
                    cp16(asA + s*aStride + 16,  ap + 4);
                    const float* wp = W + (long long)(nxt*16 + b_k) * ldw + col0 + b_n;
                    cp16(bsB + s*bStride,            wp);
                    cp16(bsB + s*bStride + 8*72*4,   wp + 8ll*ldw);
                }
                CP_COMMIT();
            }
            const int buf = i & (NSTAGE-1);
            #pragma unroll
            for (int ks = 0; ks < 2; ks++) {
                const int k0 = ks * 8;
                uint32_t a[2][4], b[4][2];
                #pragma unroll
                for (int mb = 0; mb < 2; mb++) {
                    int r0 = wm*32 + mb*16 + gp;
                    a[mb][0] = cvt_tf(As[buf][r0  ][k0 + tg]);
                    a[mb][1] = cvt_tf(As[buf][r0+8][k0 + tg]);
                    a[mb][2] = cvt_tf(As[buf][r0  ][k0 + 4 + tg]);
                    a[mb][3] = cvt_tf(As[buf][r0+8][k0 + 4 + tg]);
                }
                #pragma unroll
                for (int nb = 0; nb < 4; nb++) {
                    int cc = wn*32 + nb*8 + gp;
                    b[nb][0] = cvt_tf(Bs[buf][k0 + tg    ][cc]);
                    b[nb][1] = cvt_tf(Bs[buf][k0 + 4 + tg][cc]);
                }
                #pragma unroll
                for (int mb = 0; mb < 2; mb++)
                    #pragma unroll
                    for (int nb = 0; nb < 4; nb++)
                        mma_tf32(c[mb][nb], a[mb], b[nb]);
            }
        }
    } else {
        // ------------------ register-prefetch path with A2 fusion ------------------
        const float* A2row = A2 + (long long)bz * Ab + (long long)(row0 + a_r) * lda;
        float4 av0, av1, bv0, bv1;
        {
            const float* ap = Arow + a_k;
            av0 = *(const float4*)ap; av1 = *(const float4*)(ap + 4);
            const float* a2 = A2row + a_k;
            float4 b0 = *(const float4*)a2, b1 = *(const float4*)(a2 + 4);
            av0.x+=b0.x; av0.y+=b0.y; av0.z+=b0.z; av0.w+=b0.w;
            av1.x+=b1.x; av1.y+=b1.y; av1.z+=b1.z; av1.w+=b1.w;
            const float* wp = W + (long long)b_k * ldw + col0 + b_n;
            bv0 = *(const float4*)wp;
            bv1 = *(const float4*)(wp + 8ll * ldw);
        }
        int buf = 0;
        for (int kb = 0; kb < K; kb += 16) {
            {
                uint32_t* as = &As[buf][a_r][a_k];
                as[0]=f2tf32(av0.x); as[1]=f2tf32(av0.y); as[2]=f2tf32(av0.z); as[3]=f2tf32(av0.w);
                as[4]=f2tf32(av1.x); as[5]=f2tf32(av1.y); as[6]=f2tf32(av1.z); as[7]=f2tf32(av1.w);
                uint32_t* bs0 = &Bs[buf][b_k][b_n];
                bs0[0]=f2tf32(bv0.x); bs0[1]=f2tf32(bv0.y); bs0[2]=f2tf32(bv0.z); bs0[3]=f2tf32(bv0.w);
                uint32_t* bs1 = &Bs[buf][b_k + 8][b_n];
                bs1[0]=f2tf32(bv1.x); bs1[1]=f2tf32(bv1.y); bs1[2]=f2tf32(bv1.z); bs1[3]=f2tf32(bv1.w);
            }
            __syncthreads();
            if (kb + 16 < K) {
                const float* ap = Arow + (kb + 16) + a_k;
                av0 = *(const float4*)ap; av1 = *(const float4*)(ap + 4);
                const float* a2 = A2row + (kb + 16) + a_k;
                float4 b0 = *(const float4*)a2, b1 = *(const float4*)(a2 + 4);
                av0.x+=b0.x; av0.y+=b0.y; av0.z+=b0.z; av0.w+=b0.w;
                av1.x+=b1.x; av1.y+=b1.y; av1.z+=b1.z; av1.w+=b1.w;
                const float* wp = W + (long long)(kb + 16 + b_k) * ldw + col0 + b_n;
                bv0 = *(const float4*)wp;
                bv1 = *(const float4*)(wp + 8ll * ldw);
            }
            #pragma unroll
            for (int ks = 0; ks < 2; ks++) {
                const int k0 = ks * 8;
                uint32_t a[2][4], b[4][2];
                #pragma unroll
                for (int mb = 0; mb < 2; mb++) {
                    int r0 = wm*32 + mb*16 + gp;
                    a[mb][0] = As[buf][r0  ][k0 + tg];
                    a[mb][1] = As[buf][r0+8][k0 + tg];
                    a[mb][2] = As[buf][r0  ][k0 + 4 + tg];
                    a[mb][3] = As[buf][r0+8][k0 + 4 + tg];
                }
                #pragma unroll
                for (int nb = 0; nb < 4; nb++) {
                    int cc = wn*32 + nb*8 + gp;
                    b[nb][0] = Bs[buf][k0 + tg    ][cc];
                    b[nb][1] = Bs[buf][k0 + 4 + tg][cc];
                }
                #pragma unroll
                for (int mb = 0; mb < 2; mb++)
                    #pragma unroll
                    for (int nb = 0; nb < 4; nb++)
                        mma_tf32(c[mb][nb], a[mb], b[nb]);
            }
            buf ^= 1;
        }
    }

    #pragma unroll
    for (int mb = 0; mb < 2; mb++) {
        #pragma unroll
        for (int half = 0; half < 2; half++) {
            long long gr = row0 + wm*32 + mb*16 + gp + half*8;
            #pragma unroll
            for (int nb = 0; nb < 4; nb++) {
                #pragma unroll
                for (int j = 0; j < 2; j++) {
                    int gn = col0 + wn*32 + nb*8 + tg*2 + j;
                    float v = c[mb][nb][half*2 + j];
                    if (biasp) v += biasp[gn];
                    if (ACT==1) v = siluf(v);
                    if (ACT==2) v = softplusf(v);
                    C[gr*ldc + gn] = v;
                }
            }
        }
    }
}

__global__ void silu_flip_k(const float* __restrict__ hs0, float* __restrict__ sx,
                            float* __restrict__ sz, float* __restrict__ fx,
                            float* __restrict__ fz)
{
    int i = blockIdx.x*256 + threadIdx.x;
    if (i >= MR*DFF) return;
    int d = i & (DFF-1);
    int m = i >> 9;
    int b = m >> 9, tt = m & (LSEQ-1);
    float s1 = siluf(hs0[m*1024 + d]);
    float s2 = siluf(hs0[m*1024 + 512 + d]);
    sx[i] = s1; sz[i] = s2;
    int mf = (b << 9) + (LSEQ-1 - tt);
    fx[mf*DFF + d] = siluf(s1);
    fz[mf*DFF + d] = siluf(s2);
}

__global__ void scan_k(const float* __restrict__ delta, const float* __restrict__ u,
                       const float* __restrict__ Bm, int ldb,
                       const float* __restrict__ Alog,
                       float* __restrict__ hsum, int D, int nseq)
{
    int tid = blockIdx.x*256 + threadIdx.x;
    int n = tid & 15;
    int seg = tid >> 4;
    int d = seg % D;
    int s = seg / D;
    if (s >= nseq) return;
    float An = -expf(Alog[n]);
    float h = 0.f;
    int base = s * LSEQ;
    #pragma unroll 4
    for (int ts = 0; ts < LSEQ; ts++) {
        int r = base + ts;
        float dl = delta[r*D + d];
        float ul = u[r*D + d];
        float Bv = Bm[(long long)r*ldb + n];
        float a = expf(dl * An);
        h = fmaf(a, h, dl * ul * Bv);
        float v = h;
        v += __shfl_xor_sync(0xffffffffu, v, 1);
        v += __shfl_xor_sync(0xffffffffu, v, 2);
        v += __shfl_xor_sync(0xffffffffu, v, 4);
        v += __shfl_xor_sync(0xffffffffu, v, 8);
        if (n == 0) hsum[r*D + d] = v;
    }
}

__global__ void qk_k(const float* __restrict__ u, int D,
                     const float* __restrict__ qw, const float* __restrict__ qb,
                     const float* __restrict__ dbcd, int Np,
                     const float* __restrict__ kw, const float* __restrict__ kb,
                     float* __restrict__ qbuf, float* __restrict__ kbuf)
{
    int t = threadIdx.x;
    int c = t & 15, r16 = t >> 4;
    long long row = (long long)blockIdx.x * 16 + r16;
    const float* ar = u + row * D;
    float acc = 0.f;
    #pragma unroll 4
    for (int k = 0; k < D; k += 4) {
        float4 a4 = *(const float4*)(ar + k);
        acc = fmaf(a4.x, qw[(k+0)*16 + c], acc);
        acc = fmaf(a4.y, qw[(k+1)*16 + c], acc);
        acc = fmaf(a4.z, qw[(k+2)*16 + c], acc);
        acc = fmaf(a4.w, qw[(k+3)*16 + c], acc);
    }
    qbuf[row*16 + c] = softplusf(acc + qb[c]);
    const float* cr = dbcd + row * Np + 48;
    float acck = 0.f;
    #pragma unroll
    for (int k = 0; k < 16; k++) acck = fmaf(cr[k], kw[k*16 + c], acck);
    kbuf[row*16 + c] = softplusf(acck + kb[c]);
}

__global__ void attn_k(const float* __restrict__ q, const float* __restrict__ k,
                       float* __restrict__ attn)
{
    const int i = blockIdx.x, s = blockIdx.y;
    __shared__ float qs[16];
    __shared__ float red[16];
    const int t = threadIdx.x;  // 256
    if (t < 16) qs[t] = q[(s*LSEQ + i)*16 + t];
    __syncthreads();
    float v[2];
    #pragma unroll
    for (int jj = 0; jj < 2; jj++) {
        int j = t + jj*256;
        const float4* kr = (const float4*)(k + (long long)(s*LSEQ + j)*16);
        float4 k0 = kr[0], k1 = kr[1], k2 = kr[2], k3 = kr[3];
        float sc = qs[0]*k0.x + qs[1]*k0.y + qs[2]*k0.z + qs[3]*k0.w
                 + qs[4]*k1.x + qs[5]*k1.y + qs[6]*k1.z + qs[7]*k1.w
                 + qs[8]*k2.x + qs[9]*k2.y + qs[10]*k2.z + qs[11]*k2.w
                 + qs[12]*k3.x + qs[13]*k3.y + qs[14]*k3.z + qs[15]*k3.w;
        v[jj] = sc * (1.0f/16.0f);
    }
    float m = fmaxf(v[0], v[1]);
    for (int o=16;o;o>>=1) m = fmaxf(m, __shfl_xor_sync(0xffffffffu, m, o));
    if ((t&31)==0) red[t>>5] = m;
    __syncthreads();
    if (t == 0) { float mm = red[0]; for (int w=1;w<8;w++) mm = fmaxf(mm, red[w]); red[0] = mm; }
    __syncthreads();
    float bm = red[0];
    v[0] = expf(v[0]-bm); v[1] = expf(v[1]-bm);
    float sm = v[0] + v[1];
    for (int o=16;o;o>>=1) sm += __shfl_xor_sync(0xffffffffu, sm, o);
    if ((t&31)==0) red[8 + (t>>5)] = sm;
    __syncthreads();
    if (t == 0) { float ss = 0.f; for (int w=0;w<8;w++) ss += red[8+w]; red[8] = ss; }
    __syncthreads();
    float inv = 1.0f / red[8];
    float* arow = attn + ((long long)s*LSEQ + i)*LSEQ;
    arow[t]     = v[0]*inv;
    arow[t+256] = v[1]*inv;
}

__global__ void addmul_cat_k(float* __restrict__ y, const float* __restrict__ dbcd,
                             const float* __restrict__ u, int D, int Np)
{
    int i = blockIdx.x*256 + threadIdx.x;
    if (i >= MR*2*D) return;
    int m = i / (2*D), d = i - m*(2*D);
    int sr = (d < D) ? m : m + MR;
    int pd = (d < D) ? d : d - D;
    y[i] += dbcd[(long long)sr*Np + 64 + pd] * u[(long long)sr*D + pd];
}

__global__ void flip_k(const float* __restrict__ src, float* __restrict__ dst, int D)
{
    int i = blockIdx.x*256 + threadIdx.x;
    if (i >= MR*D) return;
    int d = i % D; int m = i / D;
    int b = m >> 9, tt = m & (LSEQ-1);
    dst[((b<<9) + (LSEQ-1 - tt))*D + d] = src[i];
}

// ---------------------------------------------------------------------------
// Host side
// ---------------------------------------------------------------------------
static inline void gemm(int act, int fa2, cudaStream_t st,
                        const float* A, const float* A2, const float* W, const float* bias,
                        float* C, int M, int N, int K, int lda, int ldw, int ldc,
                        int bat = 1, long long Ab = 0, long long Wb = 0, long long Cb = 0,
                        long long biasb = 0)
{
    dim3 g(N / 64, M / 64, bat), b(128);
    if (fa2) {
        if (act == 1) gemm_tc<1,1><<<g, b, 0, st>>>(A, A2, W, bias, C, M, N, K, lda, ldw, ldc, Ab, Wb, Cb, biasb);
        else          gemm_tc<0,1><<<g, b, 0, st>>>(A, A2, W, bias, C, M, N, K, lda, ldw, ldc, Ab, Wb, Cb, biasb);
    } else if (act == 0) {
        gemm_tc<0,0><<<g, b, 0, st>>>(A, A2, W, bias, C, M, N, K, lda, ldw, ldc, Ab, Wb, Cb, biasb);
    } else {
        gemm_tc<2,0><<<g, b, 0, st>>>(A, A2, W, bias, C, M, N, K, lda, ldw, ldc, Ab, Wb, Cb, biasb);
    }
}

// Merged-pair SSM writing concat layout ycat[2048 x 2D].
static void ssm_cat(cudaStream_t st, cudaStream_t side,
                    cudaEvent_t eA, cudaEvent_t eScan, cudaEvent_t eAttn, cudaEvent_t eY2,
                    const float* u, int D, const float* projw, int Np,
                    const float* dtw, const float* dtb, const float* Alog,
                    const float* qw, const float* qb, const float* kw, const float* kb,
                    bool useD, float* ycat,
                    float* dbcd, float* delta, float* hsum, float* qbuf, float* kbuf,
                    float* attn)
{
    gemm(0, 0, st, u, nullptr, projw, nullptr, dbcd, MR2, Np, D, D, Np, Np);
    cudaEventRecord(eA, st);
    gemm(2, 0, st, dbcd, nullptr, dtw, dtb, delta, MR2, D, 32, Np, D, D);   // softplus
    scan_k<<<(8*D*16)/256, 256, 0, st>>>(delta, u, dbcd + 32, Np, Alog, hsum, D, 8);
    cudaEventRecord(eScan, st);

    cudaStreamWaitEvent(side, eA, 0);
    qk_k<<<MR2/16, 256, 0, side>>>(u, D, qw, qb, dbcd, Np, kw, kb, qbuf, kbuf);
    attn_k<<<dim3(LSEQ, 8), 256, 0, side>>>(qbuf, kbuf, attn);
    cudaEventRecord(eAttn, side);
    cudaStreamWaitEvent(side, eScan, 0);
    gemm(0, 0, side, attn + 4ll*LSEQ*LSEQ, nullptr, hsum + 4ll*LSEQ*D, nullptr, ycat + D,
         LSEQ, D, LSEQ, LSEQ, D, 2*D,
         4, (long long)LSEQ*LSEQ, (long long)LSEQ*D, (long long)LSEQ*2*D);
    cudaEventRecord(eY2, side);

    cudaStreamWaitEvent(st, eAttn, 0);
    gemm(0, 0, st, attn, nullptr, hsum, nullptr, ycat,
         LSEQ, D, LSEQ, LSEQ, D, 2*D,
         4, (long long)LSEQ*LSEQ, (long long)LSEQ*D, (long long)LSEQ*2*D);
    cudaStreamWaitEvent(st, eY2, 0);
    if (useD) addmul_cat_k<<<(MR*2*D)/256, 256, 0, st>>>(ycat, dbcd, u, D, Np);
}

extern "C" void kernel_launch(void* const* d_in, const int* in_sizes, int n_in,
                              void* d_out, int out_size)
{
    (void)in_sizes; (void)n_in; (void)out_size;

    static cudaStream_t s1 = nullptr, s2 = nullptr, s3 = nullptr;
    static cudaEvent_t ev[12];
    if (!s1) {
        cudaStreamCreateWithFlags(&s1, cudaStreamNonBlocking);
        cudaStreamCreateWithFlags(&s2, cudaStreamNonBlocking);
        cudaStreamCreateWithFlags(&s3, cudaStreamNonBlocking);
        for (int i = 0; i < 12; i++) cudaEventCreateWithFlags(&ev[i], cudaEventDisableTiming);
    }
    cudaStream_t s0 = 0;

    float* S = nullptr;
    cudaGetSymbolAddress((void**)&S, g_scratch);

    float* hs0    = S;                  // 2048*1024
    float* usx    = hs0    + 2097152;   // [4096 x 512]
    float* ufb    = usx    + 2097152;   // [4096 x 512]
    float* ub     = ufb    + 2097152;   // [4096 x 256]
    float* dbcdF  = ub     + 1048576;   // 4096*576
    float* deltaF = dbcdF  + 2359296;   // 4096*512
    float* hsumF  = deltaF + 2097152;   // 4096*512
    float* qbufF  = hsumF  + 2097152;   // 4096*16
    float* kbufF  = qbufF  + 65536;
    float* attnF  = kbufF  + 65536;     // 8*512*512
    float* dbcdB  = attnF  + 2097152;   // 4096*320
    float* deltaB = dbcdB  + 1310720;   // 4096*256
    float* hsumB  = deltaB + 1048576;   // 4096*256
    float* qbufB  = hsumB  + 1048576;   // 4096*16
    float* kbufB  = qbufB  + 65536;
    float* attnB  = kbufB  + 65536;     // 8*512*512
    float* ycatF  = attnB  + 2097152;   // [2048 x 1024]
    float* ybcatB = ycatF  + 2097152;   // [2048 x 512]
    float* cat2   = ybcatB + 1048576;   // 2048*1024
    float* oe     = cat2   + 2097152;   // 2048*256
    float* oef    = oe     + 524288;    // 2048*256
    float* xbuf   = oef    + 524288;    // 2048*512

    const float* x             = (const float*)d_in[0];
    const float* in_w          = (const float*)d_in[1];
    const float* in_b          = (const float*)d_in[2];
    const float* x_proj_w      = (const float*)d_in[3];
    const float* dt_w          = (const float*)d_in[4];
    const float* dt_b          = (const float*)d_in[5];
    const float* A_log         = (const float*)d_in[6];
    const float* exit_x_w      = (const float*)d_in[7];
    const float* exit_x_b      = (const float*)d_in[8];
    const float* exit_z_w      = (const float*)d_in[9];
    const float* exit_z_b      = (const float*)d_in[10];
    const float* x_proj_exit_w = (const float*)d_in[11];
    const float* dt_exit_w     = (const float*)d_in[12];
    const float* dt_exit_b     = (const float*)d_in[13];
    const float* A_log_exit    = (const float*)d_in[14];
    const float* out_inner_w   = (const float*)d_in[15];
    const float* out_inner_b   = (const float*)d_in[16];
    const float* out_exit_w    = (const float*)d_in[17];
    const float* out_exit_b    = (const float*)d_in[18];
    const float* up_w          = (const float*)d_in[19];
    const float* up_b          = (const float*)d_in[20];
    const float* out_w         = (const float*)d_in[21];
    const float* out_b         = (const float*)d_in[22];
    const float* q_in_w        = (const float*)d_in[23];
    const float* q_in_b        = (const float*)d_in[24];
    const float* k_in_w        = (const float*)d_in[25];
    const float* k_in_b        = (const float*)d_in[26];
    const float* q_ex_w        = (const float*)d_in[27];
    const float* q_ex_b        = (const float*)d_in[28];
    const float* k_ex_w        = (const float*)d_in[29];
    const float* k_ex_b        = (const float*)d_in[30];

    const float* cur = x;
    for (int l = 0; l < 2; l++) {
        const float* in_w_l = in_w + (long long)l*512*1024;
        const float* in_b_l = in_b + l*1024;
        const float* xp_l   = x_proj_w + (long long)l*512*576;
        const float* dtw_l  = dt_w + l*32*512;
        const float* dtb_l  = dt_b + l*512;
        const float* Al_l   = A_log + l*16;
        const float* exw_l  = exit_x_w + (long long)l*512*256;
        const float* exb_l  = exit_x_b + l*256;
        const float* ezw_l  = exit_z_w + (long long)l*512*256;
        const float* ezb_l  = exit_z_b + l*256;
        const float* xpe_l  = x_proj_exit_w + (long long)l*256*320;
        const float* dtew_l = dt_exit_w + l*32*256;
        const float* dteb_l = dt_exit_b + l*256;
        const float* Ale_l  = A_log_exit + l*16;
        const float* oiw_l  = out_inner_w + (long long)l*1024*512;
        const float* oib_l  = out_inner_b + l*512;
        const float* oew_l  = out_exit_w + (long long)l*512*256;
        const float* oeb_l  = out_exit_b + l*256;
        const float* upw_l  = up_w + (long long)l*256*512;
        const float* upb_l  = up_b + l*512;
        const float* ow_l   = out_w + (long long)l*1024*512;
        const float* ob_l   = out_b + l*512;
        const float* qiw_l  = q_in_w + l*512*16;
        const float* qib_l  = q_in_b + l*16;
        const float* kiw_l  = k_in_w + l*16*16;
        const float* kib_l  = k_in_b + l*16;
        const float* qew_l  = q_ex_w + l*256*16;
        const float* qeb_l  = q_ex_b + l*16;
        const float* kew_l  = k_ex_w + l*16*16;
        const float* keb_l  = k_ex_b + l*16;

        // ---- serial head
        gemm(0, 0, s0, cur, nullptr, in_w_l, in_b_l, hs0, MR, 1024, 512, 512, 1024, 1024);
        silu_flip_k<<<(MR*DFF)/256, 256, 0, s0>>>(hs0, usx, usx + MR*DFF,
                                                  ufb, ufb + MR*DFF);

        // ---- FORK backward chain onto s1
        cudaEventRecord(ev[8], s0);
        cudaStreamWaitEvent(s1, ev[8], 0);

        gemm(0, 0, s1, ufb, nullptr, exw_l, exb_l, ub, MR, 256, 512, 512, 256, 256,
             2, (long long)MR*512, (long long)(ezw_l - exw_l), (long long)MR*256,
             (long long)(ezb_l - exb_l));
        ssm_cat(s1, s3, ev[4], ev[5], ev[6], ev[7],
                ub, 256, xpe_l, 320, dtew_l, dteb_l, Ale_l,
                qew_l, qeb_l, kew_l, keb_l, false, ybcatB,
                dbcdB, deltaB, hsumB, qbufB, kbufB, attnB);
        gemm(0, 0, s1, ybcatB, nullptr, oew_l, oeb_l, oe, MR, 256, 512, 512, 256, 256);
        flip_k<<<(MR*256)/256, 256, 0, s1>>>(oe, oef, 256);
        gemm(0, 0, s1, oef, nullptr, upw_l, upb_l, cat2 + 512, MR, 512, 256, 256, 512, 1024);
        cudaEventRecord(ev[9], s1);

        // s0 (concurrent): forward SSM + out_inner
        ssm_cat(s0, s2, ev[0], ev[1], ev[2], ev[3],
                usx, 512, xp_l, 576, dtw_l, dtb_l, Al_l,
                qiw_l, qib_l, kiw_l, kib_l, true, ycatF,
                dbcdF, deltaF, hsumF, qbufF, kbufF, attnF);
        gemm(0, 0, s0, ycatF, nullptr, oiw_l, oib_l, cat2, MR, 512, 1024, 1024, 512, 1024);

        // ---- JOIN: out projection with fused residual (A2 = hs0);
        //      layer 1 fuses final silu and writes d_out directly.
        cudaStreamWaitEvent(s0, ev[9], 0);
        {
            float* dst = (l == 1) ? (float*)d_out : xbuf;
            gemm((l == 1) ? 1 : 0, 1, s0, cat2, hs0, ow_l, ob_l, dst,
                 MR, 512, 1024, 1024, 512, 512);
        }
        cur = xbuf;
    }
}